// round 10
// baseline (speedup 1.0000x reference)
#include <cuda_runtime.h>
#include <cooperative_groups.h>
#include <cstdint>
#include <cstddef>

namespace cg = cooperative_groups;
typedef unsigned long long ull;

// ---------------------------------------------------------------------------
// Problem constants (fixed by setup_inputs)
// ---------------------------------------------------------------------------
constexpr int B  = 4;
constexpr int N  = 16384;
constexpr int C  = 16;
constexpr int S  = 1024;       // npoint
constexpr int NS = 64;         // NSAMPLE
constexpr int NG = B * S;                 // 4096 groups
constexpr int M  = NG * NS;               // 262144 columns
constexpr int CIN1 = 3 + C;               // 19
constexpr int GB = M / 128;               // 2048 gemm blocks

// FPS cluster decomposition: 4 CTAs x 1024 threads per batch
constexpr int CL      = 4;                // CTAs per cluster (one cluster per batch)
constexpr int FPS_T   = 1024;             // threads per CTA (32 warps)
constexpr int PPT     = N / CL / FPS_T;   // 4 points per thread
constexpr int SLICE   = N / CL;           // 4096 points per CTA
constexpr int NW      = FPS_T / 32;       // 32 warps

// Output layout: new_xyz (B,S,3) | new_features (B,128,S) | inds (B,S), all f32
constexpr int OUT_FEAT = B * S * 3;              // 12288
constexpr int OUT_INDS = OUT_FEAT + B * 128 * S; // 536576

// ---------------------------------------------------------------------------
// Scratch (device globals; no runtime allocation allowed)
// ---------------------------------------------------------------------------
__device__ float g_newxyz[NG * 3];
__device__ int   g_idx[NG * NS];
__device__ float g_X0[(size_t)CIN1 * M];     // ~20 MB
__device__ float g_Y2[(size_t)64 * M];       // 67 MB
__device__ float g_max3[(size_t)128 * NG];   // 2 MB
__device__ float g_part[(size_t)128 * GB * 2]; // deterministic BN partials
__device__ float g_scl1[64],  g_shf1[64];
__device__ float g_scl2[64],  g_shf2[64];
__device__ float g_scl3[128], g_shf3[128];

// ---------------------------------------------------------------------------
// DSMEM primitives
// ---------------------------------------------------------------------------
__device__ __forceinline__ uint32_t mapa_sh(uint32_t local, uint32_t rank) {
    uint32_t r;
    asm("mapa.shared::cluster.u32 %0, %1, %2;" : "=r"(r) : "r"(local), "r"(rank));
    return r;
}
__device__ __forceinline__ void st_cluster_u64(uint32_t addr, ull v) {
    asm volatile("st.shared::cluster.u64 [%0], %1;" :: "r"(addr), "l"(v) : "memory");
}
__device__ __forceinline__ void st_cluster_v4(uint32_t addr, uint32_t a, uint32_t b2,
                                              uint32_t c2, uint32_t d2) {
    asm volatile("st.shared::cluster.v4.b32 [%0], {%1,%2,%3,%4};"
                 :: "r"(addr), "r"(a), "r"(b2), "r"(c2), "r"(d2) : "memory");
}

// ---------------------------------------------------------------------------
// 1) Furthest point sampling — 4-CTA cluster per batch, 1024 thr/CTA (PPT=4).
//    Hierarchical exchange (R9 structure): warp winners -> local smem ->
//    block REDUX by warp0 -> ONE key+coords pushed per peer ->
//    cluster.sync -> 4-slot resolve per warp.
//    Distance arithmetic and tie-breaks identical to the passing R2-R9.
// ---------------------------------------------------------------------------
__global__ void __launch_bounds__(FPS_T, 1) __cluster_dims__(CL, 1, 1)
fps_kernel(const float* __restrict__ xyz, float* __restrict__ out)
{
    __shared__ ull    wkey[NW];
    __shared__ float4 wxyz[NW];
    __shared__ ull    skey[2][CL];
    __shared__ float4 sxyz[2][CL];

    cg::cluster_group cluster = cg::this_cluster();
    const unsigned rank = cluster.block_rank();
    const int b = blockIdx.x / CL;
    const float* __restrict__ p = xyz + (size_t)b * N * 3;
    const int t = threadIdx.x;
    const int lane = t & 31, wid = t >> 5;
    const int jbase = rank * SLICE + t;

    float X[PPT], Y[PPT], Z[PPT], D[PPT];
#pragma unroll
    for (int k = 0; k < PPT; k++) {
        int j = jbase + k * FPS_T;
        X[k] = p[3 * j];
        Y[k] = p[3 * j + 1];
        Z[k] = p[3 * j + 2];
        D[k] = 1e10f;
    }

    // warp0 lanes 0..3: remote slot addresses (lane r targets rank r, slot=our rank)
    uint32_t ak0 = 0, ak1 = 0, ax0 = 0, ax1 = 0;
    if (wid == 0) {
        uint32_t k0 = (uint32_t)__cvta_generic_to_shared(&skey[0][rank]);
        uint32_t k1 = (uint32_t)__cvta_generic_to_shared(&skey[1][rank]);
        uint32_t x0 = (uint32_t)__cvta_generic_to_shared(&sxyz[0][rank]);
        uint32_t x1 = (uint32_t)__cvta_generic_to_shared(&sxyz[1][rank]);
        uint32_t tr = (uint32_t)(lane & (CL - 1));
        ak0 = mapa_sh(k0, tr); ak1 = mapa_sh(k1, tr);
        ax0 = mapa_sh(x0, tr); ax1 = mapa_sh(x1, tr);
    }

    int far = 0;
    float cx = p[0], cy = p[1], cz = p[2];

    for (int i = 0; i < S; i++) {
        if (rank == 0 && t == 0) {
            int gi = b * S + i;
            g_newxyz[3 * gi]     = cx;
            g_newxyz[3 * gi + 1] = cy;
            g_newxyz[3 * gi + 2] = cz;
            out[3 * gi]     = cx;
            out[3 * gi + 1] = cy;
            out[3 * gi + 2] = cz;
            out[OUT_INDS + gi] = (float)far;
        }

        // distance update + per-thread argmax with coordinate payload (exact)
        float best = -1.0f, bx = 0.f, by = 0.f, bz = 0.f;
        int bj = 0;
#pragma unroll
        for (int k = 0; k < PPT; k++) {
            float dx = __fadd_rn(X[k], -cx);
            float dy = __fadd_rn(Y[k], -cy);
            float dz = __fadd_rn(Z[k], -cz);
            float d  = __fadd_rn(__fadd_rn(__fmul_rn(dx, dx), __fmul_rn(dy, dy)),
                                 __fmul_rn(dz, dz));
            float nd = fminf(D[k], d);
            D[k] = nd;
            if (nd > best) {
                best = nd; bx = X[k]; by = Y[k]; bz = Z[k];
                bj = jbase + k * FPS_T;
            }
        }

        // warp argmax via two-stage REDUX; winner lane stores key+coords (no shfls)
        unsigned mb = __float_as_uint(best);                 // dist >= 0
        unsigned H  = __reduce_max_sync(0xffffffffu, mb);
        bool     el = (mb == H);
        unsigned lo = el ? (unsigned)(N - 1 - bj) : 0u;
        unsigned L  = __reduce_max_sync(0xffffffffu, lo);
        int wbj = N - 1 - (int)L;
        unsigned bal = __ballot_sync(0xffffffffu, el && (bj == wbj));
        int src = __ffs(bal) - 1;
        if (lane == src) {
            wkey[wid] = ((ull)H << 32) | L;
            wxyz[wid] = make_float4(bx, by, bz, 0.f);
        }
        __syncthreads();

        const int par = i & 1;
        if (wid == 0) {
            // block winner over 32 warp slots (one per lane)
            ull k2 = wkey[lane];
            unsigned kh = (unsigned)(k2 >> 32);
            unsigned BH = __reduce_max_sync(0xffffffffu, kh);
            unsigned kl = (kh == BH) ? (unsigned)k2 : 0u;
            unsigned BL = __reduce_max_sync(0xffffffffu, kl);
            ull BW = ((ull)BH << 32) | BL;
            unsigned bw = __ballot_sync(0xffffffffu, k2 == BW);
            int ws = __ffs(bw) - 1;
            float4 wc = wxyz[ws];          // LDS broadcast (same addr all lanes)
            if (lane < CL) {
                st_cluster_u64(par ? ak1 : ak0, BW);
                st_cluster_v4(par ? ax1 : ax0, __float_as_uint(wc.x),
                              __float_as_uint(wc.y), __float_as_uint(wc.z), 0u);
            }
        }
        cluster.sync();

        // per-warp resolve over the 4 CTA-winner slots
        ull a = 0;
        if (lane < CL) a = skey[par][lane];
        unsigned ch = (unsigned)(a >> 32);
        unsigned RH = __reduce_max_sync(0xffffffffu, ch);
        unsigned cl2 = (ch == RH) ? (unsigned)a : 0u;
        unsigned RL = __reduce_max_sync(0xffffffffu, cl2);
        ull W = ((ull)RH << 32) | RL;
        unsigned bal2 = __ballot_sync(0xffffffffu, (lane < CL) && (a == W));
        int slot = __ffs(bal2) - 1;
        float4 cc = sxyz[par][slot];       // LDS broadcast
        cx = cc.x; cy = cc.y; cz = cc.z;
        far = N - 1 - (int)RL;
    }
}

// ---------------------------------------------------------------------------
// 2) Ball query: one warp per center, ordered first-NS collection via ballot.
// ---------------------------------------------------------------------------
__global__ void ball_kernel(const float* __restrict__ xyz)
{
    int gw = (blockIdx.x * blockDim.x + threadIdx.x) >> 5;
    if (gw >= NG) return;
    int lane = threadIdx.x & 31;
    int b = gw >> 10;
    const float* __restrict__ p = xyz + (size_t)b * N * 3;
    float cx = g_newxyz[3 * gw], cy = g_newxyz[3 * gw + 1], cz = g_newxyz[3 * gw + 2];
    int* outp = g_idx + gw * NS;

    int cnt = 0, first = 0;
    for (int base = 0; base < N; base += 32) {
        int j = base + lane;
        float dx = __fadd_rn(p[3 * j],     -cx);
        float dy = __fadd_rn(p[3 * j + 1], -cy);
        float dz = __fadd_rn(p[3 * j + 2], -cz);
        float d  = __fadd_rn(__fadd_rn(__fmul_rn(dx, dx), __fmul_rn(dy, dy)),
                             __fmul_rn(dz, dz));
        bool hit = d < 0.16f;
        unsigned mask = __ballot_sync(0xffffffffu, hit);
        if (mask) {
            if (cnt == 0) first = base + __ffs(mask) - 1;
            int pos = cnt + __popc(mask & ((1u << lane) - 1u));
            if (hit && pos < NS) outp[pos] = j;
            cnt += __popc(mask);
            if (cnt >= NS) break;
        }
    }
    for (int q = cnt + lane; q < NS; q += 32) outp[q] = first;
}

// ---------------------------------------------------------------------------
// 3) Grouping: build X0 [19][M] (normalized xyz + gathered features)
// ---------------------------------------------------------------------------
__global__ void group_kernel(const float* __restrict__ xyz,
                             const float* __restrict__ feat)
{
    int m = blockIdx.x * blockDim.x + threadIdx.x;
    if (m >= M) return;
    int g = m >> 6;
    int b = g >> 10;
    int j = g_idx[m];
    const float* p = xyz + ((size_t)b * N + j) * 3;
    float cx = g_newxyz[3 * g], cy = g_newxyz[3 * g + 1], cz = g_newxyz[3 * g + 2];
    g_X0[(size_t)0 * M + m] = (p[0] - cx) * 2.5f;
    g_X0[(size_t)1 * M + m] = (p[1] - cy) * 2.5f;
    g_X0[(size_t)2 * M + m] = (p[2] - cz) * 2.5f;
    const float* fb = feat + (size_t)b * C * N + j;
#pragma unroll
    for (int c = 0; c < C; c++)
        g_X0[(size_t)(3 + c) * M + m] = fb[(size_t)c * N];
}

// ---------------------------------------------------------------------------
// 4a) Pass 1: BN1 partials from X0 (no Y1 materialization).
// ---------------------------------------------------------------------------
__global__ void __launch_bounds__(256)
gemm_p1(const float* __restrict__ Wg)
{
    __shared__ float Ws[CIN1 * 64];
    __shared__ float Xs[CIN1 * 128];

    const int tid = threadIdx.x;
    const int m0  = blockIdx.x * 128;
    const int tx  = tid & 15, ty = tid >> 4;

    for (int i = tid; i < CIN1 * 64; i += 256) {
        int c = i >> 6, o = i & 63;
        Ws[i] = Wg[o * CIN1 + c];
    }
    for (int i = tid; i < CIN1 * 32; i += 256) {
        int r = i >> 5, c4 = i & 31;
        *reinterpret_cast<float4*>(Xs + r * 128 + c4 * 4) =
            *reinterpret_cast<const float4*>(g_X0 + (size_t)r * M + m0 + c4 * 4);
    }
    __syncthreads();

    float acc[4][8];
#pragma unroll
    for (int i = 0; i < 4; i++)
#pragma unroll
        for (int jj = 0; jj < 8; jj++) acc[i][jj] = 0.f;

#pragma unroll 4
    for (int k = 0; k < CIN1; k++) {
        float4 w4 = *reinterpret_cast<const float4*>(Ws + k * 64 + ty * 4);
        float4 xa = *reinterpret_cast<const float4*>(Xs + k * 128 + tx * 8);
        float4 xb = *reinterpret_cast<const float4*>(Xs + k * 128 + tx * 8 + 4);
        float wr[4] = {w4.x, w4.y, w4.z, w4.w};
        float xr[8] = {xa.x, xa.y, xa.z, xa.w, xb.x, xb.y, xb.z, xb.w};
#pragma unroll
        for (int i = 0; i < 4; i++)
#pragma unroll
            for (int jj = 0; jj < 8; jj++)
                acc[i][jj] = fmaf(wr[i], xr[jj], acc[i][jj]);
    }

#pragma unroll
    for (int i = 0; i < 4; i++) {
        float sm = 0.f, sq = 0.f;
#pragma unroll
        for (int jj = 0; jj < 8; jj++) {
            sm += acc[i][jj];
            sq += acc[i][jj] * acc[i][jj];
        }
#pragma unroll
        for (int o = 8; o > 0; o >>= 1) {
            sm += __shfl_xor_sync(0xffffffffu, sm, o);
            sq += __shfl_xor_sync(0xffffffffu, sq, o);
        }
        if (tx == 0) {
            int o = ty * 4 + i;
            g_part[((size_t)o * GB + blockIdx.x) * 2]     = sm;
            g_part[((size_t)o * GB + blockIdx.x) * 2 + 1] = sq;
        }
    }
}

// ---------------------------------------------------------------------------
// 4b) Pass 2: recompute Y1 tile from X0 (bit-identical fmaf order), apply
//     BN1+ReLU in smem, then 64-out GEMM -> Y2 + BN2 partials.
// ---------------------------------------------------------------------------
constexpr int L2_SMEM = (CIN1 * 64 + 64 * 64 + CIN1 * 128 + 64 * 128) * 4;

__global__ void __launch_bounds__(256)
gemm_l2(const float* __restrict__ W1g, const float* __restrict__ W2g)
{
    extern __shared__ float sm_[];
    float* W1s = sm_;                          // [c][o] 19x64
    float* W2s = W1s + CIN1 * 64;              // [k][o] 64x64
    float* X0s = W2s + 64 * 64;                // [c][col] 19x128
    float* Y1s = X0s + CIN1 * 128;             // [k][col] 64x128

    const int tid = threadIdx.x;
    const int m0  = blockIdx.x * 128;
    const int tx  = tid & 15, ty = tid >> 4;

    for (int i = tid; i < CIN1 * 64; i += 256) {
        int c = i >> 6, o = i & 63;
        W1s[i] = W1g[o * CIN1 + c];
    }
    for (int i = tid; i < 64 * 64; i += 256) {
        int k = i >> 6, o = i & 63;
        W2s[i] = W2g[o * 64 + k];
    }
    for (int i = tid; i < CIN1 * 32; i += 256) {
        int r = i >> 5, c4 = i & 31;
        *reinterpret_cast<float4*>(X0s + r * 128 + c4 * 4) =
            *reinterpret_cast<const float4*>(g_X0 + (size_t)r * M + m0 + c4 * 4);
    }
    __syncthreads();

    // stage 1: Y1n = relu(bn1(W1 . X0)) — same acc order as pass 1
    {
        float a1[4][8];
#pragma unroll
        for (int i = 0; i < 4; i++)
#pragma unroll
            for (int jj = 0; jj < 8; jj++) a1[i][jj] = 0.f;
#pragma unroll 4
        for (int c = 0; c < CIN1; c++) {
            float4 w4 = *reinterpret_cast<const float4*>(W1s + c * 64 + ty * 4);
            float4 xa = *reinterpret_cast<const float4*>(X0s + c * 128 + tx * 8);
            float4 xb = *reinterpret_cast<const float4*>(X0s + c * 128 + tx * 8 + 4);
            float wr[4] = {w4.x, w4.y, w4.z, w4.w};
            float xr[8] = {xa.x, xa.y, xa.z, xa.w, xb.x, xb.y, xb.z, xb.w};
#pragma unroll
            for (int i = 0; i < 4; i++)
#pragma unroll
                for (int jj = 0; jj < 8; jj++)
                    a1[i][jj] = fmaf(wr[i], xr[jj], a1[i][jj]);
        }
#pragma unroll
        for (int i = 0; i < 4; i++) {
            int o = ty * 4 + i;
            float sc = g_scl1[o], sh = g_shf1[o];
            float4 va, vb;
            va.x = fmaxf(fmaf(a1[i][0], sc, sh), 0.f);
            va.y = fmaxf(fmaf(a1[i][1], sc, sh), 0.f);
            va.z = fmaxf(fmaf(a1[i][2], sc, sh), 0.f);
            va.w = fmaxf(fmaf(a1[i][3], sc, sh), 0.f);
            vb.x = fmaxf(fmaf(a1[i][4], sc, sh), 0.f);
            vb.y = fmaxf(fmaf(a1[i][5], sc, sh), 0.f);
            vb.z = fmaxf(fmaf(a1[i][6], sc, sh), 0.f);
            vb.w = fmaxf(fmaf(a1[i][7], sc, sh), 0.f);
            *reinterpret_cast<float4*>(Y1s + o * 128 + tx * 8)     = va;
            *reinterpret_cast<float4*>(Y1s + o * 128 + tx * 8 + 4) = vb;
        }
    }
    __syncthreads();

    // stage 2: Y2 = W2 . Y1n
    float acc[4][8];
#pragma unroll
    for (int i = 0; i < 4; i++)
#pragma unroll
        for (int jj = 0; jj < 8; jj++) acc[i][jj] = 0.f;

#pragma unroll 4
    for (int k = 0; k < 64; k++) {
        float4 w4 = *reinterpret_cast<const float4*>(W2s + k * 64 + ty * 4);
        float4 xa = *reinterpret_cast<const float4*>(Y1s + k * 128 + tx * 8);
        float4 xb = *reinterpret_cast<const float4*>(Y1s + k * 128 + tx * 8 + 4);
        float wr[4] = {w4.x, w4.y, w4.z, w4.w};
        float xr[8] = {xa.x, xa.y, xa.z, xa.w, xb.x, xb.y, xb.z, xb.w};
#pragma unroll
        for (int i = 0; i < 4; i++)
#pragma unroll
            for (int jj = 0; jj < 8; jj++)
                acc[i][jj] = fmaf(wr[i], xr[jj], acc[i][jj]);
    }

#pragma unroll
    for (int i = 0; i < 4; i++) {
        size_t off = (size_t)(ty * 4 + i) * M + m0 + tx * 8;
        *reinterpret_cast<float4*>(g_Y2 + off) =
            make_float4(acc[i][0], acc[i][1], acc[i][2], acc[i][3]);
        *reinterpret_cast<float4*>(g_Y2 + off + 4) =
            make_float4(acc[i][4], acc[i][5], acc[i][6], acc[i][7]);
    }

#pragma unroll
    for (int i = 0; i < 4; i++) {
        float sm = 0.f, sq = 0.f;
#pragma unroll
        for (int jj = 0; jj < 8; jj++) {
            sm += acc[i][jj];
            sq += acc[i][jj] * acc[i][jj];
        }
#pragma unroll
        for (int o = 8; o > 0; o >>= 1) {
            sm += __shfl_xor_sync(0xffffffffu, sm, o);
            sq += __shfl_xor_sync(0xffffffffu, sq, o);
        }
        if (tx == 0) {
            int o = ty * 4 + i;
            g_part[((size_t)o * GB + blockIdx.x) * 2]     = sm;
            g_part[((size_t)o * GB + blockIdx.x) * 2 + 1] = sq;
        }
    }
}

// ---------------------------------------------------------------------------
// 4c) Pass 3: merged 128-output GEMM, fused BN2+ReLU in, partials + group max
// ---------------------------------------------------------------------------
__global__ void __launch_bounds__(256)
gemm128_l3(const float* __restrict__ Wg)   // W3: (128,64) row-major
{
    __shared__ float Ws[64 * 128];   // 32 KB
    __shared__ float Xs[32 * 128];   // 16 KB

    const int tid = threadIdx.x;
    const int m0  = blockIdx.x * 128;
    const int tx  = tid & 15, ty = tid >> 4;

    for (int i = tid; i < 64 * 128; i += 256) {
        int k = i >> 7, o = i & 127;
        Ws[i] = Wg[o * 64 + k];
    }

    float acc[8][8];
#pragma unroll
    for (int i = 0; i < 8; i++)
#pragma unroll
        for (int jj = 0; jj < 8; jj++) acc[i][jj] = 0.f;

    for (int k0 = 0; k0 < 64; k0 += 32) {
        __syncthreads();
        for (int i = tid; i < 32 * 32; i += 256) {
            int r = i >> 5, c4 = i & 31;
            float4 v = *reinterpret_cast<const float4*>(
                g_Y2 + (size_t)(k0 + r) * M + m0 + c4 * 4);
            float sc = g_scl2[k0 + r], sh = g_shf2[k0 + r];
            v.x = fmaxf(fmaf(v.x, sc, sh), 0.f);
            v.y = fmaxf(fmaf(v.y, sc, sh), 0.f);
            v.z = fmaxf(fmaf(v.z, sc, sh), 0.f);
            v.w = fmaxf(fmaf(v.w, sc, sh), 0.f);
            *reinterpret_cast<float4*>(Xs + r * 128 + c4 * 4) = v;
        }
        __syncthreads();
#pragma unroll 4
        for (int k = 0; k < 32; k++) {
            float4 wa = *reinterpret_cast<const float4*>(Ws + (k0 + k) * 128 + ty * 8);
            float4 wb = *reinterpret_cast<const float4*>(Ws + (k0 + k) * 128 + ty * 8 + 4);
            float4 xa = *reinterpret_cast<const float4*>(Xs + k * 128 + tx * 8);
            float4 xb = *reinterpret_cast<const float4*>(Xs + k * 128 + tx * 8 + 4);
            float wr[8] = {wa.x, wa.y, wa.z, wa.w, wb.x, wb.y, wb.z, wb.w};
            float xr[8] = {xa.x, xa.y, xa.z, xa.w, xb.x, xb.y, xb.z, xb.w};
#pragma unroll
            for (int i = 0; i < 8; i++)
#pragma unroll
                for (int jj = 0; jj < 8; jj++)
                    acc[i][jj] = fmaf(wr[i], xr[jj], acc[i][jj]);
        }
    }

#pragma unroll
    for (int i = 0; i < 8; i++) {
        float sm = 0.f, sq = 0.f;
#pragma unroll
        for (int jj = 0; jj < 8; jj++) {
            sm += acc[i][jj];
            sq += acc[i][jj] * acc[i][jj];
        }
#pragma unroll
        for (int o = 8; o > 0; o >>= 1) {
            sm += __shfl_xor_sync(0xffffffffu, sm, o);
            sq += __shfl_xor_sync(0xffffffffu, sq, o);
        }
        if (tx == 0) {
            int o = ty * 8 + i;
            g_part[((size_t)o * GB + blockIdx.x) * 2]     = sm;
            g_part[((size_t)o * GB + blockIdx.x) * 2 + 1] = sq;
        }
    }

#pragma unroll
    for (int i = 0; i < 8; i++) {
        float mx = acc[i][0];
#pragma unroll
        for (int jj = 1; jj < 8; jj++) mx = fmaxf(mx, acc[i][jj]);
#pragma unroll
        for (int o = 4; o > 0; o >>= 1)
            mx = fmaxf(mx, __shfl_xor_sync(0xffffffffu, mx, o));
        if ((tx & 7) == 0) {
            int grp = (m0 >> 6) + (tx >> 3);
            g_max3[(size_t)(ty * 8 + i) * NG + grp] = mx;
        }
    }
}

// ---------------------------------------------------------------------------
// 5) BN stat finalize — parallel: one block per channel, fixed-order tree.
// ---------------------------------------------------------------------------
template<int LAYER>
__global__ void fin_par(const float* __restrict__ gam,
                        const float* __restrict__ bet)
{
    float* scl = (LAYER == 1) ? g_scl1 : (LAYER == 2) ? g_scl2 : g_scl3;
    float* shf = (LAYER == 1) ? g_shf1 : (LAYER == 2) ? g_shf2 : g_shf3;
    __shared__ float ssm[256], ssq[256];
    const int o = blockIdx.x;
    const int t = threadIdx.x;
    float sm = 0.f, sq = 0.f;
    const float* pp = g_part + (size_t)o * GB * 2;
    for (int i = t; i < GB; i += 256) {
        sm += pp[2 * i];
        sq += pp[2 * i + 1];
    }
    ssm[t] = sm; ssq[t] = sq;
    __syncthreads();
#pragma unroll
    for (int s2 = 128; s2 > 0; s2 >>= 1) {
        if (t < s2) { ssm[t] += ssm[t + s2]; ssq[t] += ssq[t + s2]; }
        __syncthreads();
    }
    if (t == 0) {
        float mean = ssm[0] * (1.0f / (float)M);
        float var  = ssq[0] * (1.0f / (float)M) - mean * mean;
        float sc = gam[o] * rsqrtf(var + 1e-5f);
        scl[o] = sc;
        shf[o] = fmaf(-mean, sc, bet[o]);
    }
}

// ---------------------------------------------------------------------------
// 6) Final: normalize+ReLU the group-max, write new_features
// ---------------------------------------------------------------------------
__global__ void out_feat_kernel(float* __restrict__ out)
{
    int idx = blockIdx.x * blockDim.x + threadIdx.x;
    if (idx >= 128 * NG) return;
    int o = idx >> 12;
    int g = idx & (NG - 1);
    int b = g >> 10, s = g & 1023;
    float v = fmaxf(fmaf(g_max3[idx], g_scl3[o], g_shf3[o]), 0.f);
    out[OUT_FEAT + ((size_t)(b * 128 + o)) * S + s] = v;
}

// ---------------------------------------------------------------------------
// Launch
// ---------------------------------------------------------------------------
extern "C" void kernel_launch(void* const* d_in, const int* in_sizes, int n_in,
                              void* d_out, int out_size)
{
    (void)in_sizes; (void)n_in; (void)out_size;
    const float* xyz  = (const float*)d_in[0];
    const float* feat = (const float*)d_in[1];
    const float* W1   = (const float*)d_in[2];
    const float* g1   = (const float*)d_in[3];
    const float* b1   = (const float*)d_in[4];
    const float* W2   = (const float*)d_in[5];
    const float* g2   = (const float*)d_in[6];
    const float* b2   = (const float*)d_in[7];
    const float* W3   = (const float*)d_in[8];
    const float* g3   = (const float*)d_in[9];
    const float* b3   = (const float*)d_in[10];
    float* out = (float*)d_out;

    cudaFuncSetAttribute(gemm_l2,
                         cudaFuncAttributeMaxDynamicSharedMemorySize, L2_SMEM);

    fps_kernel<<<B * CL, FPS_T>>>(xyz, out);
    ball_kernel<<<(NG * 32) / 256, 256>>>(xyz);
    group_kernel<<<M / 256, 256>>>(xyz, feat);

    gemm_p1<<<GB, 256>>>(W1);
    fin_par<1><<<64, 256>>>(g1, b1);

    gemm_l2<<<GB, 256, L2_SMEM>>>(W1, W2);
    fin_par<2><<<64, 256>>>(g2, b2);

    gemm128_l3<<<GB, 256>>>(W3);
    fin_par<3><<<128, 256>>>(g3, b3);

    out_feat_kernel<<<(128 * NG) / 256, 256>>>(out);
}

// round 11
// speedup vs baseline: 1.1017x; 1.1017x over previous
#include <cuda_runtime.h>
#include <cooperative_groups.h>
#include <cstdint>
#include <cstddef>

namespace cg = cooperative_groups;
typedef unsigned long long ull;

// ---------------------------------------------------------------------------
// Problem constants (fixed by setup_inputs)
// ---------------------------------------------------------------------------
constexpr int B  = 4;
constexpr int N  = 16384;
constexpr int C  = 16;
constexpr int S  = 1024;       // npoint
constexpr int NS = 64;         // NSAMPLE
constexpr int NG = B * S;                 // 4096 groups
constexpr int M  = NG * NS;               // 262144 columns
constexpr int CIN1 = 3 + C;               // 19
constexpr int GB = M / 128;               // 2048 gemm blocks

// FPS cluster decomposition (R9 topology: 8 CTAs x 256 threads per batch)
constexpr int CL      = 8;                // CTAs per cluster (one cluster per batch)
constexpr int FPS_T   = 256;              // threads per CTA (8 warps)
constexpr int PPT     = N / CL / FPS_T;   // 8 points per thread
constexpr int SLICE   = N / CL;           // 2048 points per CTA
constexpr int NW      = FPS_T / 32;       // 8 warps

// Output layout: new_xyz (B,S,3) | new_features (B,128,S) | inds (B,S), all f32
constexpr int OUT_FEAT = B * S * 3;              // 12288
constexpr int OUT_INDS = OUT_FEAT + B * 128 * S; // 536576

// ---------------------------------------------------------------------------
// Scratch (device globals; no runtime allocation allowed)
// ---------------------------------------------------------------------------
__device__ float g_newxyz[NG * 3];
__device__ int   g_idx[NG * NS];
__device__ float g_X0[(size_t)CIN1 * M];     // ~20 MB
__device__ float g_Y2[(size_t)64 * M];       // 67 MB
__device__ float g_max3[(size_t)128 * NG];   // 2 MB
__device__ float g_part[(size_t)128 * GB * 2]; // deterministic BN partials
__device__ float g_scl1[64],  g_shf1[64];
__device__ float g_scl2[64],  g_shf2[64];
__device__ float g_scl3[128], g_shf3[128];

// ---------------------------------------------------------------------------
// DSMEM / mbarrier primitives
// ---------------------------------------------------------------------------
__device__ __forceinline__ uint32_t mapa_sh(uint32_t local, uint32_t rank) {
    uint32_t r;
    asm("mapa.shared::cluster.u32 %0, %1, %2;" : "=r"(r) : "r"(local), "r"(rank));
    return r;
}
__device__ __forceinline__ void st_cluster_u64(uint32_t addr, ull v) {
    asm volatile("st.shared::cluster.u64 [%0], %1;" :: "r"(addr), "l"(v) : "memory");
}
__device__ __forceinline__ void st_cluster_v4(uint32_t addr, uint32_t a, uint32_t b2,
                                              uint32_t c2, uint32_t d2) {
    asm volatile("st.shared::cluster.v4.b32 [%0], {%1,%2,%3,%4};"
                 :: "r"(addr), "r"(a), "r"(b2), "r"(c2), "r"(d2) : "memory");
}
__device__ __forceinline__ void mbar_init(uint32_t addr, uint32_t cnt) {
    asm volatile("mbarrier.init.shared.b64 [%0], %1;" :: "r"(addr), "r"(cnt) : "memory");
}
__device__ __forceinline__ void mbar_arrive_rel_cluster(uint32_t remote) {
    asm volatile("mbarrier.arrive.release.cluster.shared::cluster.b64 _, [%0];"
                 :: "r"(remote) : "memory");
}
__device__ __forceinline__ void mbar_wait_acq(uint32_t addr, uint32_t parity) {
    asm volatile(
        "{\n\t.reg .pred P;\n"
        "W%=:\n\t"
        "mbarrier.try_wait.parity.acquire.cluster.shared::cta.b64 P, [%0], %1, 0x989680;\n\t"
        "@!P bra W%=;\n\t}"
        :: "r"(addr), "r"(parity) : "memory");
}

// ---------------------------------------------------------------------------
// 1) Furthest point sampling — 8-CTA cluster per batch (R9 hierarchical
//    exchange), with per-iteration cluster.sync replaced by a CL-arrival
//    parity mbarrier (8 remote arrivals per CTA per iter, try_wait wake).
//    Distance arithmetic and tie-breaks identical to the passing R2-R10.
// ---------------------------------------------------------------------------
__global__ void __launch_bounds__(FPS_T, 1) __cluster_dims__(CL, 1, 1)
fps_kernel(const float* __restrict__ xyz, float* __restrict__ out)
{
    __shared__ ull    wkey[NW];
    __shared__ float4 wxyz[NW];
    __shared__ ull    skey[2][CL];
    __shared__ float4 sxyz[2][CL];
    __shared__ ull    barr[2];

    cg::cluster_group cluster = cg::this_cluster();
    const unsigned rank = cluster.block_rank();
    const int b = blockIdx.x >> 3;
    const float* __restrict__ p = xyz + (size_t)b * N * 3;
    const int t = threadIdx.x;
    const int lane = t & 31, wid = t >> 5;
    const int jbase = rank * SLICE + t;

    float X[PPT], Y[PPT], Z[PPT], D[PPT];
#pragma unroll
    for (int k = 0; k < PPT; k++) {
        int j = jbase + k * FPS_T;
        X[k] = p[3 * j];
        Y[k] = p[3 * j + 1];
        Z[k] = p[3 * j + 2];
        D[k] = 1e10f;
    }

    if (t == 0) {
        mbar_init((uint32_t)__cvta_generic_to_shared(&barr[0]), CL);
        mbar_init((uint32_t)__cvta_generic_to_shared(&barr[1]), CL);
    }

    // warp0 lanes 0..7: remote slot + barrier addresses (lane r targets rank r)
    uint32_t ak0 = 0, ak1 = 0, ax0 = 0, ax1 = 0, ab0 = 0, ab1 = 0;
    if (wid == 0) {
        uint32_t k0 = (uint32_t)__cvta_generic_to_shared(&skey[0][rank]);
        uint32_t k1 = (uint32_t)__cvta_generic_to_shared(&skey[1][rank]);
        uint32_t x0 = (uint32_t)__cvta_generic_to_shared(&sxyz[0][rank]);
        uint32_t x1 = (uint32_t)__cvta_generic_to_shared(&sxyz[1][rank]);
        uint32_t b0 = (uint32_t)__cvta_generic_to_shared(&barr[0]);
        uint32_t b1 = (uint32_t)__cvta_generic_to_shared(&barr[1]);
        uint32_t tr = (uint32_t)(lane & 7);
        ak0 = mapa_sh(k0, tr); ak1 = mapa_sh(k1, tr);
        ax0 = mapa_sh(x0, tr); ax1 = mapa_sh(x1, tr);
        ab0 = mapa_sh(b0, tr); ab1 = mapa_sh(b1, tr);
    }
    const uint32_t lb0 = (uint32_t)__cvta_generic_to_shared(&barr[0]);
    const uint32_t lb1 = (uint32_t)__cvta_generic_to_shared(&barr[1]);

    cluster.sync();   // one-time: barriers initialized cluster-wide

    int far = 0;
    float cx = p[0], cy = p[1], cz = p[2];
    uint32_t ph[2] = {0u, 0u};

    for (int i = 0; i < S; i++) {
        if (rank == 0 && t == 0) {
            int gi = b * S + i;
            g_newxyz[3 * gi]     = cx;
            g_newxyz[3 * gi + 1] = cy;
            g_newxyz[3 * gi + 2] = cz;
            out[3 * gi]     = cx;
            out[3 * gi + 1] = cy;
            out[3 * gi + 2] = cz;
            out[OUT_INDS + gi] = (float)far;
        }

        // distance update + per-thread argmax with coordinate payload (exact)
        float best = -1.0f, bx = 0.f, by = 0.f, bz = 0.f;
        int bj = 0;
#pragma unroll
        for (int k = 0; k < PPT; k++) {
            float dx = __fadd_rn(X[k], -cx);
            float dy = __fadd_rn(Y[k], -cy);
            float dz = __fadd_rn(Z[k], -cz);
            float d  = __fadd_rn(__fadd_rn(__fmul_rn(dx, dx), __fmul_rn(dy, dy)),
                                 __fmul_rn(dz, dz));
            float nd = fminf(D[k], d);
            D[k] = nd;
            if (nd > best) {
                best = nd; bx = X[k]; by = Y[k]; bz = Z[k];
                bj = jbase + k * FPS_T;
            }
        }

        // warp argmax via two-stage REDUX; winner lane stores key+coords (no shfls)
        unsigned mb = __float_as_uint(best);                 // dist >= 0
        unsigned H  = __reduce_max_sync(0xffffffffu, mb);
        bool     el = (mb == H);
        unsigned lo = el ? (unsigned)(N - 1 - bj) : 0u;
        unsigned L  = __reduce_max_sync(0xffffffffu, lo);
        int wbj = N - 1 - (int)L;
        unsigned bal = __ballot_sync(0xffffffffu, el && (bj == wbj));
        int src = __ffs(bal) - 1;
        if (lane == src) {
            wkey[wid] = ((ull)H << 32) | L;
            wxyz[wid] = make_float4(bx, by, bz, 0.f);
        }
        __syncthreads();

        const int par = i & 1;
        if (wid == 0) {
            // block winner over 8 warp slots (keys duplicated across lane groups)
            ull k2 = wkey[lane & 7];
            unsigned kh = (unsigned)(k2 >> 32);
            unsigned BH = __reduce_max_sync(0xffffffffu, kh);
            unsigned kl = (kh == BH) ? (unsigned)k2 : 0u;
            unsigned BL = __reduce_max_sync(0xffffffffu, kl);
            ull BW = ((ull)BH << 32) | BL;
            unsigned bw = __ballot_sync(0xffffffffu, (lane < 8) && (k2 == BW));
            int ws = __ffs(bw) - 1;
            float4 wc = wxyz[ws];          // LDS broadcast (same addr all lanes)
            if (lane < CL) {
                st_cluster_u64(par ? ak1 : ak0, BW);
                st_cluster_v4(par ? ax1 : ax0, __float_as_uint(wc.x),
                              __float_as_uint(wc.y), __float_as_uint(wc.z), 0u);
                mbar_arrive_rel_cluster(par ? ab1 : ab0);   // release: slots visible
            }
        }

        mbar_wait_acq(par ? lb1 : lb0, ph[par]);
        ph[par] ^= 1u;

        // per-warp resolve over the 8 CTA-winner slots
        ull a = 0;
        if (lane < CL) a = skey[par][lane];
        unsigned ch = (unsigned)(a >> 32);
        unsigned RH = __reduce_max_sync(0xffffffffu, ch);
        unsigned cl2 = (ch == RH) ? (unsigned)a : 0u;
        unsigned RL = __reduce_max_sync(0xffffffffu, cl2);
        ull W = ((ull)RH << 32) | RL;
        unsigned bal2 = __ballot_sync(0xffffffffu, (lane < CL) && (a == W));
        int slot = __ffs(bal2) - 1;
        float4 cc = sxyz[par][slot];       // LDS broadcast
        cx = cc.x; cy = cc.y; cz = cc.z;
        far = N - 1 - (int)RL;
    }
    cluster.sync();   // no CTA exits while peers may still write our smem
}

// ---------------------------------------------------------------------------
// 2) Ball query: one warp per center, ordered first-NS collection via ballot.
// ---------------------------------------------------------------------------
__global__ void ball_kernel(const float* __restrict__ xyz)
{
    int gw = (blockIdx.x * blockDim.x + threadIdx.x) >> 5;
    if (gw >= NG) return;
    int lane = threadIdx.x & 31;
    int b = gw >> 10;
    const float* __restrict__ p = xyz + (size_t)b * N * 3;
    float cx = g_newxyz[3 * gw], cy = g_newxyz[3 * gw + 1], cz = g_newxyz[3 * gw + 2];
    int* outp = g_idx + gw * NS;

    int cnt = 0, first = 0;
    for (int base = 0; base < N; base += 32) {
        int j = base + lane;
        float dx = __fadd_rn(p[3 * j],     -cx);
        float dy = __fadd_rn(p[3 * j + 1], -cy);
        float dz = __fadd_rn(p[3 * j + 2], -cz);
        float d  = __fadd_rn(__fadd_rn(__fmul_rn(dx, dx), __fmul_rn(dy, dy)),
                             __fmul_rn(dz, dz));
        bool hit = d < 0.16f;
        unsigned mask = __ballot_sync(0xffffffffu, hit);
        if (mask) {
            if (cnt == 0) first = base + __ffs(mask) - 1;
            int pos = cnt + __popc(mask & ((1u << lane) - 1u));
            if (hit && pos < NS) outp[pos] = j;
            cnt += __popc(mask);
            if (cnt >= NS) break;
        }
    }
    for (int q = cnt + lane; q < NS; q += 32) outp[q] = first;
}

// ---------------------------------------------------------------------------
// 3) Grouping: build X0 [19][M] (normalized xyz + gathered features)
// ---------------------------------------------------------------------------
__global__ void group_kernel(const float* __restrict__ xyz,
                             const float* __restrict__ feat)
{
    int m = blockIdx.x * blockDim.x + threadIdx.x;
    if (m >= M) return;
    int g = m >> 6;
    int b = g >> 10;
    int j = g_idx[m];
    const float* p = xyz + ((size_t)b * N + j) * 3;
    float cx = g_newxyz[3 * g], cy = g_newxyz[3 * g + 1], cz = g_newxyz[3 * g + 2];
    g_X0[(size_t)0 * M + m] = (p[0] - cx) * 2.5f;
    g_X0[(size_t)1 * M + m] = (p[1] - cy) * 2.5f;
    g_X0[(size_t)2 * M + m] = (p[2] - cz) * 2.5f;
    const float* fb = feat + (size_t)b * C * N + j;
#pragma unroll
    for (int c = 0; c < C; c++)
        g_X0[(size_t)(3 + c) * M + m] = fb[(size_t)c * N];
}

// ---------------------------------------------------------------------------
// 4a) Pass 1: BN1 partials from X0 (no Y1 materialization).
// ---------------------------------------------------------------------------
__global__ void __launch_bounds__(256)
gemm_p1(const float* __restrict__ Wg)
{
    __shared__ float Ws[CIN1 * 64];
    __shared__ float Xs[CIN1 * 128];

    const int tid = threadIdx.x;
    const int m0  = blockIdx.x * 128;
    const int tx  = tid & 15, ty = tid >> 4;

    for (int i = tid; i < CIN1 * 64; i += 256) {
        int c = i >> 6, o = i & 63;
        Ws[i] = Wg[o * CIN1 + c];
    }
    for (int i = tid; i < CIN1 * 32; i += 256) {
        int r = i >> 5, c4 = i & 31;
        *reinterpret_cast<float4*>(Xs + r * 128 + c4 * 4) =
            *reinterpret_cast<const float4*>(g_X0 + (size_t)r * M + m0 + c4 * 4);
    }
    __syncthreads();

    float acc[4][8];
#pragma unroll
    for (int i = 0; i < 4; i++)
#pragma unroll
        for (int jj = 0; jj < 8; jj++) acc[i][jj] = 0.f;

#pragma unroll 4
    for (int k = 0; k < CIN1; k++) {
        float4 w4 = *reinterpret_cast<const float4*>(Ws + k * 64 + ty * 4);
        float4 xa = *reinterpret_cast<const float4*>(Xs + k * 128 + tx * 8);
        float4 xb = *reinterpret_cast<const float4*>(Xs + k * 128 + tx * 8 + 4);
        float wr[4] = {w4.x, w4.y, w4.z, w4.w};
        float xr[8] = {xa.x, xa.y, xa.z, xa.w, xb.x, xb.y, xb.z, xb.w};
#pragma unroll
        for (int i = 0; i < 4; i++)
#pragma unroll
            for (int jj = 0; jj < 8; jj++)
                acc[i][jj] = fmaf(wr[i], xr[jj], acc[i][jj]);
    }

#pragma unroll
    for (int i = 0; i < 4; i++) {
        float sm = 0.f, sq = 0.f;
#pragma unroll
        for (int jj = 0; jj < 8; jj++) {
            sm += acc[i][jj];
            sq += acc[i][jj] * acc[i][jj];
        }
#pragma unroll
        for (int o = 8; o > 0; o >>= 1) {
            sm += __shfl_xor_sync(0xffffffffu, sm, o);
            sq += __shfl_xor_sync(0xffffffffu, sq, o);
        }
        if (tx == 0) {
            int o = ty * 4 + i;
            g_part[((size_t)o * GB + blockIdx.x) * 2]     = sm;
            g_part[((size_t)o * GB + blockIdx.x) * 2 + 1] = sq;
        }
    }
}

// ---------------------------------------------------------------------------
// 4b) Pass 2: recompute Y1 tile from X0 (bit-identical fmaf order), apply
//     BN1+ReLU in smem, then 64-out GEMM -> Y2 + BN2 partials.
// ---------------------------------------------------------------------------
constexpr int L2_SMEM = (CIN1 * 64 + 64 * 64 + CIN1 * 128 + 64 * 128) * 4;

__global__ void __launch_bounds__(256)
gemm_l2(const float* __restrict__ W1g, const float* __restrict__ W2g)
{
    extern __shared__ float sm_[];
    float* W1s = sm_;                          // [c][o] 19x64
    float* W2s = W1s + CIN1 * 64;              // [k][o] 64x64
    float* X0s = W2s + 64 * 64;                // [c][col] 19x128
    float* Y1s = X0s + CIN1 * 128;             // [k][col] 64x128

    const int tid = threadIdx.x;
    const int m0  = blockIdx.x * 128;
    const int tx  = tid & 15, ty = tid >> 4;

    for (int i = tid; i < CIN1 * 64; i += 256) {
        int c = i >> 6, o = i & 63;
        W1s[i] = W1g[o * CIN1 + c];
    }
    for (int i = tid; i < 64 * 64; i += 256) {
        int k = i >> 6, o = i & 63;
        W2s[i] = W2g[o * 64 + k];
    }
    for (int i = tid; i < CIN1 * 32; i += 256) {
        int r = i >> 5, c4 = i & 31;
        *reinterpret_cast<float4*>(X0s + r * 128 + c4 * 4) =
            *reinterpret_cast<const float4*>(g_X0 + (size_t)r * M + m0 + c4 * 4);
    }
    __syncthreads();

    // stage 1: Y1n = relu(bn1(W1 . X0)) — same acc order as pass 1
    {
        float a1[4][8];
#pragma unroll
        for (int i = 0; i < 4; i++)
#pragma unroll
            for (int jj = 0; jj < 8; jj++) a1[i][jj] = 0.f;
#pragma unroll 4
        for (int c = 0; c < CIN1; c++) {
            float4 w4 = *reinterpret_cast<const float4*>(W1s + c * 64 + ty * 4);
            float4 xa = *reinterpret_cast<const float4*>(X0s + c * 128 + tx * 8);
            float4 xb = *reinterpret_cast<const float4*>(X0s + c * 128 + tx * 8 + 4);
            float wr[4] = {w4.x, w4.y, w4.z, w4.w};
            float xr[8] = {xa.x, xa.y, xa.z, xa.w, xb.x, xb.y, xb.z, xb.w};
#pragma unroll
            for (int i = 0; i < 4; i++)
#pragma unroll
                for (int jj = 0; jj < 8; jj++)
                    a1[i][jj] = fmaf(wr[i], xr[jj], a1[i][jj]);
        }
#pragma unroll
        for (int i = 0; i < 4; i++) {
            int o = ty * 4 + i;
            float sc = g_scl1[o], sh = g_shf1[o];
            float4 va, vb;
            va.x = fmaxf(fmaf(a1[i][0], sc, sh), 0.f);
            va.y = fmaxf(fmaf(a1[i][1], sc, sh), 0.f);
            va.z = fmaxf(fmaf(a1[i][2], sc, sh), 0.f);
            va.w = fmaxf(fmaf(a1[i][3], sc, sh), 0.f);
            vb.x = fmaxf(fmaf(a1[i][4], sc, sh), 0.f);
            vb.y = fmaxf(fmaf(a1[i][5], sc, sh), 0.f);
            vb.z = fmaxf(fmaf(a1[i][6], sc, sh), 0.f);
            vb.w = fmaxf(fmaf(a1[i][7], sc, sh), 0.f);
            *reinterpret_cast<float4*>(Y1s + o * 128 + tx * 8)     = va;
            *reinterpret_cast<float4*>(Y1s + o * 128 + tx * 8 + 4) = vb;
        }
    }
    __syncthreads();

    // stage 2: Y2 = W2 . Y1n
    float acc[4][8];
#pragma unroll
    for (int i = 0; i < 4; i++)
#pragma unroll
        for (int jj = 0; jj < 8; jj++) acc[i][jj] = 0.f;

#pragma unroll 4
    for (int k = 0; k < 64; k++) {
        float4 w4 = *reinterpret_cast<const float4*>(W2s + k * 64 + ty * 4);
        float4 xa = *reinterpret_cast<const float4*>(Y1s + k * 128 + tx * 8);
        float4 xb = *reinterpret_cast<const float4*>(Y1s + k * 128 + tx * 8 + 4);
        float wr[4] = {w4.x, w4.y, w4.z, w4.w};
        float xr[8] = {xa.x, xa.y, xa.z, xa.w, xb.x, xb.y, xb.z, xb.w};
#pragma unroll
        for (int i = 0; i < 4; i++)
#pragma unroll
            for (int jj = 0; jj < 8; jj++)
                acc[i][jj] = fmaf(wr[i], xr[jj], acc[i][jj]);
    }

#pragma unroll
    for (int i = 0; i < 4; i++) {
        size_t off = (size_t)(ty * 4 + i) * M + m0 + tx * 8;
        *reinterpret_cast<float4*>(g_Y2 + off) =
            make_float4(acc[i][0], acc[i][1], acc[i][2], acc[i][3]);
        *reinterpret_cast<float4*>(g_Y2 + off + 4) =
            make_float4(acc[i][4], acc[i][5], acc[i][6], acc[i][7]);
    }

#pragma unroll
    for (int i = 0; i < 4; i++) {
        float sm = 0.f, sq = 0.f;
#pragma unroll
        for (int jj = 0; jj < 8; jj++) {
            sm += acc[i][jj];
            sq += acc[i][jj] * acc[i][jj];
        }
#pragma unroll
        for (int o = 8; o > 0; o >>= 1) {
            sm += __shfl_xor_sync(0xffffffffu, sm, o);
            sq += __shfl_xor_sync(0xffffffffu, sq, o);
        }
        if (tx == 0) {
            int o = ty * 4 + i;
            g_part[((size_t)o * GB + blockIdx.x) * 2]     = sm;
            g_part[((size_t)o * GB + blockIdx.x) * 2 + 1] = sq;
        }
    }
}

// ---------------------------------------------------------------------------
// 4c) Pass 3: merged 128-output GEMM, fused BN2+ReLU in, partials + group max
// ---------------------------------------------------------------------------
__global__ void __launch_bounds__(256)
gemm128_l3(const float* __restrict__ Wg)   // W3: (128,64) row-major
{
    __shared__ float Ws[64 * 128];   // 32 KB
    __shared__ float Xs[32 * 128];   // 16 KB

    const int tid = threadIdx.x;
    const int m0  = blockIdx.x * 128;
    const int tx  = tid & 15, ty = tid >> 4;

    for (int i = tid; i < 64 * 128; i += 256) {
        int k = i >> 7, o = i & 127;
        Ws[i] = Wg[o * 64 + k];
    }

    float acc[8][8];
#pragma unroll
    for (int i = 0; i < 8; i++)
#pragma unroll
        for (int jj = 0; jj < 8; jj++) acc[i][jj] = 0.f;

    for (int k0 = 0; k0 < 64; k0 += 32) {
        __syncthreads();
        for (int i = tid; i < 32 * 32; i += 256) {
            int r = i >> 5, c4 = i & 31;
            float4 v = *reinterpret_cast<const float4*>(
                g_Y2 + (size_t)(k0 + r) * M + m0 + c4 * 4);
            float sc = g_scl2[k0 + r], sh = g_shf2[k0 + r];
            v.x = fmaxf(fmaf(v.x, sc, sh), 0.f);
            v.y = fmaxf(fmaf(v.y, sc, sh), 0.f);
            v.z = fmaxf(fmaf(v.z, sc, sh), 0.f);
            v.w = fmaxf(fmaf(v.w, sc, sh), 0.f);
            *reinterpret_cast<float4*>(Xs + r * 128 + c4 * 4) = v;
        }
        __syncthreads();
#pragma unroll 4
        for (int k = 0; k < 32; k++) {
            float4 wa = *reinterpret_cast<const float4*>(Ws + (k0 + k) * 128 + ty * 8);
            float4 wb = *reinterpret_cast<const float4*>(Ws + (k0 + k) * 128 + ty * 8 + 4);
            float4 xa = *reinterpret_cast<const float4*>(Xs + k * 128 + tx * 8);
            float4 xb = *reinterpret_cast<const float4*>(Xs + k * 128 + tx * 8 + 4);
            float wr[8] = {wa.x, wa.y, wa.z, wa.w, wb.x, wb.y, wb.z, wb.w};
            float xr[8] = {xa.x, xa.y, xa.z, xa.w, xb.x, xb.y, xb.z, xb.w};
#pragma unroll
            for (int i = 0; i < 8; i++)
#pragma unroll
                for (int jj = 0; jj < 8; jj++)
                    acc[i][jj] = fmaf(wr[i], xr[jj], acc[i][jj]);
        }
    }

#pragma unroll
    for (int i = 0; i < 8; i++) {
        float sm = 0.f, sq = 0.f;
#pragma unroll
        for (int jj = 0; jj < 8; jj++) {
            sm += acc[i][jj];
            sq += acc[i][jj] * acc[i][jj];
        }
#pragma unroll
        for (int o = 8; o > 0; o >>= 1) {
            sm += __shfl_xor_sync(0xffffffffu, sm, o);
            sq += __shfl_xor_sync(0xffffffffu, sq, o);
        }
        if (tx == 0) {
            int o = ty * 8 + i;
            g_part[((size_t)o * GB + blockIdx.x) * 2]     = sm;
            g_part[((size_t)o * GB + blockIdx.x) * 2 + 1] = sq;
        }
    }

#pragma unroll
    for (int i = 0; i < 8; i++) {
        float mx = acc[i][0];
#pragma unroll
        for (int jj = 1; jj < 8; jj++) mx = fmaxf(mx, acc[i][jj]);
#pragma unroll
        for (int o = 4; o > 0; o >>= 1)
            mx = fmaxf(mx, __shfl_xor_sync(0xffffffffu, mx, o));
        if ((tx & 7) == 0) {
            int grp = (m0 >> 6) + (tx >> 3);
            g_max3[(size_t)(ty * 8 + i) * NG + grp] = mx;
        }
    }
}

// ---------------------------------------------------------------------------
// 5) BN stat finalize — parallel: one block per channel, fixed-order tree.
// ---------------------------------------------------------------------------
template<int LAYER>
__global__ void fin_par(const float* __restrict__ gam,
                        const float* __restrict__ bet)
{
    float* scl = (LAYER == 1) ? g_scl1 : (LAYER == 2) ? g_scl2 : g_scl3;
    float* shf = (LAYER == 1) ? g_shf1 : (LAYER == 2) ? g_shf2 : g_shf3;
    __shared__ float ssm[256], ssq[256];
    const int o = blockIdx.x;
    const int t = threadIdx.x;
    float sm = 0.f, sq = 0.f;
    const float* pp = g_part + (size_t)o * GB * 2;
    for (int i = t; i < GB; i += 256) {
        sm += pp[2 * i];
        sq += pp[2 * i + 1];
    }
    ssm[t] = sm; ssq[t] = sq;
    __syncthreads();
#pragma unroll
    for (int s2 = 128; s2 > 0; s2 >>= 1) {
        if (t < s2) { ssm[t] += ssm[t + s2]; ssq[t] += ssq[t + s2]; }
        __syncthreads();
    }
    if (t == 0) {
        float mean = ssm[0] * (1.0f / (float)M);
        float var  = ssq[0] * (1.0f / (float)M) - mean * mean;
        float sc = gam[o] * rsqrtf(var + 1e-5f);
        scl[o] = sc;
        shf[o] = fmaf(-mean, sc, bet[o]);
    }
}

// ---------------------------------------------------------------------------
// 6) Final: normalize+ReLU the group-max, write new_features
// ---------------------------------------------------------------------------
__global__ void out_feat_kernel(float* __restrict__ out)
{
    int idx = blockIdx.x * blockDim.x + threadIdx.x;
    if (idx >= 128 * NG) return;
    int o = idx >> 12;
    int g = idx & (NG - 1);
    int b = g >> 10, s = g & 1023;
    float v = fmaxf(fmaf(g_max3[idx], g_scl3[o], g_shf3[o]), 0.f);
    out[OUT_FEAT + ((size_t)(b * 128 + o)) * S + s] = v;
}

// ---------------------------------------------------------------------------
// Launch
// ---------------------------------------------------------------------------
extern "C" void kernel_launch(void* const* d_in, const int* in_sizes, int n_in,
                              void* d_out, int out_size)
{
    (void)in_sizes; (void)n_in; (void)out_size;
    const float* xyz  = (const float*)d_in[0];
    const float* feat = (const float*)d_in[1];
    const float* W1   = (const float*)d_in[2];
    const float* g1   = (const float*)d_in[3];
    const float* b1   = (const float*)d_in[4];
    const float* W2   = (const float*)d_in[5];
    const float* g2   = (const float*)d_in[6];
    const float* b2   = (const float*)d_in[7];
    const float* W3   = (const float*)d_in[8];
    const float* g3   = (const float*)d_in[9];
    const float* b3   = (const float*)d_in[10];
    float* out = (float*)d_out;

    cudaFuncSetAttribute(gemm_l2,
                         cudaFuncAttributeMaxDynamicSharedMemorySize, L2_SMEM);

    fps_kernel<<<B * CL, FPS_T>>>(xyz, out);
    ball_kernel<<<(NG * 32) / 256, 256>>>(xyz);
    group_kernel<<<M / 256, 256>>>(xyz, feat);

    gemm_p1<<<GB, 256>>>(W1);
    fin_par<1><<<64, 256>>>(g1, b1);

    gemm_l2<<<GB, 256, L2_SMEM>>>(W1, W2);
    fin_par<2><<<64, 256>>>(g2, b2);

    gemm128_l3<<<GB, 256>>>(W3);
    fin_par<3><<<128, 256>>>(g3, b3);

    out_feat_kernel<<<(128 * NG) / 256, 256>>>(out);
}

// round 13
// speedup vs baseline: 1.2467x; 1.1316x over previous
#include <cuda_runtime.h>
#include <cooperative_groups.h>
#include <cstdint>
#include <cstddef>

namespace cg = cooperative_groups;
typedef unsigned long long ull;

// ---------------------------------------------------------------------------
// Problem constants (fixed by setup_inputs)
// ---------------------------------------------------------------------------
constexpr int B  = 4;
constexpr int N  = 16384;
constexpr int C  = 16;
constexpr int S  = 1024;       // npoint
constexpr int NS = 64;         // NSAMPLE
constexpr int NG = B * S;                 // 4096 groups
constexpr int M  = NG * NS;               // 262144 columns
constexpr int CIN1 = 3 + C;               // 19
constexpr int GB = M / 128;               // 2048 gemm blocks

// FPS cluster decomposition (R9 topology: 8 CTAs x 256 threads per batch)
constexpr int CL      = 8;                // CTAs per cluster (one cluster per batch)
constexpr int FPS_T   = 256;              // threads per CTA (8 warps)
constexpr int PPT     = N / CL / FPS_T;   // 8 points per thread
constexpr int SLICE   = N / CL;           // 2048 points per CTA
constexpr int NW      = FPS_T / 32;       // 8 warps

// Output layout: new_xyz (B,S,3) | new_features (B,128,S) | inds (B,S), all f32
constexpr int OUT_FEAT = B * S * 3;              // 12288
constexpr int OUT_INDS = OUT_FEAT + B * 128 * S; // 536576

// ---------------------------------------------------------------------------
// Scratch (device globals; no runtime allocation allowed)
// ---------------------------------------------------------------------------
__device__ float g_newxyz[NG * 3];
__device__ float g_X0[(size_t)CIN1 * M];     // ~20 MB
__device__ float g_Y2[(size_t)64 * M];       // 67 MB
__device__ float g_max3[(size_t)128 * NG];   // 2 MB
__device__ float g_part[(size_t)128 * GB * 2]; // deterministic BN partials
__device__ float g_scl1[64],  g_shf1[64];
__device__ float g_scl2[64],  g_shf2[64];
__device__ float g_scl3[128], g_shf3[128];

// ---------------------------------------------------------------------------
// DSMEM primitives
// ---------------------------------------------------------------------------
__device__ __forceinline__ uint32_t mapa_sh(uint32_t local, uint32_t rank) {
    uint32_t r;
    asm("mapa.shared::cluster.u32 %0, %1, %2;" : "=r"(r) : "r"(local), "r"(rank));
    return r;
}
__device__ __forceinline__ void st_cluster_u64(uint32_t addr, ull v) {
    asm volatile("st.shared::cluster.u64 [%0], %1;" :: "r"(addr), "l"(v) : "memory");
}
__device__ __forceinline__ void st_cluster_v4(uint32_t addr, uint32_t a, uint32_t b2,
                                              uint32_t c2, uint32_t d2) {
    asm volatile("st.shared::cluster.v4.b32 [%0], {%1,%2,%3,%4};"
                 :: "r"(addr), "r"(a), "r"(b2), "r"(c2), "r"(d2) : "memory");
}

// ---------------------------------------------------------------------------
// 1) Furthest point sampling — R9 hierarchical exchange + cluster.sync
//    (the proven-best mechanism). ONE change vs R9: the per-iteration
//    output stores run on warp 1 (t==32), not warp 0 — warp 0 is the
//    stage-B pacing warp and gates the cluster.sync release.
// ---------------------------------------------------------------------------
__global__ void __launch_bounds__(FPS_T, 1) __cluster_dims__(CL, 1, 1)
fps_kernel(const float* __restrict__ xyz, float* __restrict__ out)
{
    __shared__ ull    wkey[NW];
    __shared__ float4 wxyz[NW];
    __shared__ ull    skey[2][CL];
    __shared__ float4 sxyz[2][CL];

    cg::cluster_group cluster = cg::this_cluster();
    const unsigned rank = cluster.block_rank();
    const int b = blockIdx.x >> 3;
    const float* __restrict__ p = xyz + (size_t)b * N * 3;
    const int t = threadIdx.x;
    const int lane = t & 31, wid = t >> 5;
    const int jbase = rank * SLICE + t;

    float X[PPT], Y[PPT], Z[PPT], D[PPT];
#pragma unroll
    for (int k = 0; k < PPT; k++) {
        int j = jbase + k * FPS_T;
        X[k] = p[3 * j];
        Y[k] = p[3 * j + 1];
        Z[k] = p[3 * j + 2];
        D[k] = 1e10f;
    }

    // warp0 lanes 0..7: remote slot addresses (lane r targets rank r, slot=our rank)
    uint32_t ak0 = 0, ak1 = 0, ax0 = 0, ax1 = 0;
    if (wid == 0) {
        uint32_t k0 = (uint32_t)__cvta_generic_to_shared(&skey[0][rank]);
        uint32_t k1 = (uint32_t)__cvta_generic_to_shared(&skey[1][rank]);
        uint32_t x0 = (uint32_t)__cvta_generic_to_shared(&sxyz[0][rank]);
        uint32_t x1 = (uint32_t)__cvta_generic_to_shared(&sxyz[1][rank]);
        uint32_t tr = (uint32_t)(lane & 7);
        ak0 = mapa_sh(k0, tr); ak1 = mapa_sh(k1, tr);
        ax0 = mapa_sh(x0, tr); ax1 = mapa_sh(x1, tr);
    }

    int far = 0;
    float cx = p[0], cy = p[1], cz = p[2];

    for (int i = 0; i < S; i++) {
        // outputs on warp 1 (all threads hold identical cx/cy/cz/far)
        if (rank == 0 && t == 32) {
            int gi = b * S + i;
            g_newxyz[3 * gi]     = cx;
            g_newxyz[3 * gi + 1] = cy;
            g_newxyz[3 * gi + 2] = cz;
            out[3 * gi]     = cx;
            out[3 * gi + 1] = cy;
            out[3 * gi + 2] = cz;
            out[OUT_INDS + gi] = (float)far;
        }

        // distance update + per-thread argmax with coordinate payload (exact)
        float best = -1.0f, bx = 0.f, by = 0.f, bz = 0.f;
        int bj = 0;
#pragma unroll
        for (int k = 0; k < PPT; k++) {
            float dx = __fadd_rn(X[k], -cx);
            float dy = __fadd_rn(Y[k], -cy);
            float dz = __fadd_rn(Z[k], -cz);
            float d  = __fadd_rn(__fadd_rn(__fmul_rn(dx, dx), __fmul_rn(dy, dy)),
                                 __fmul_rn(dz, dz));
            float nd = fminf(D[k], d);
            D[k] = nd;
            if (nd > best) {
                best = nd; bx = X[k]; by = Y[k]; bz = Z[k];
                bj = jbase + k * FPS_T;
            }
        }

        // warp argmax via two-stage REDUX; winner lane stores key+coords (no shfls)
        unsigned mb = __float_as_uint(best);                 // dist >= 0
        unsigned H  = __reduce_max_sync(0xffffffffu, mb);
        bool     el = (mb == H);
        unsigned lo = el ? (unsigned)(N - 1 - bj) : 0u;
        unsigned L  = __reduce_max_sync(0xffffffffu, lo);
        int wbj = N - 1 - (int)L;
        unsigned bal = __ballot_sync(0xffffffffu, el && (bj == wbj));
        int src = __ffs(bal) - 1;
        if (lane == src) {
            wkey[wid] = ((ull)H << 32) | L;
            wxyz[wid] = make_float4(bx, by, bz, 0.f);
        }
        __syncthreads();

        const int par = i & 1;
        if (wid == 0) {
            // block winner over 8 warp slots (keys duplicated across lane groups)
            ull k2 = wkey[lane & 7];
            unsigned kh = (unsigned)(k2 >> 32);
            unsigned BH = __reduce_max_sync(0xffffffffu, kh);
            unsigned kl = (kh == BH) ? (unsigned)k2 : 0u;
            unsigned BL = __reduce_max_sync(0xffffffffu, kl);
            ull BW = ((ull)BH << 32) | BL;
            unsigned bw = __ballot_sync(0xffffffffu, (lane < 8) && (k2 == BW));
            int ws = __ffs(bw) - 1;
            float4 wc = wxyz[ws];          // LDS broadcast (same addr all lanes)
            if (lane < CL) {
                st_cluster_u64(par ? ak1 : ak0, BW);
                st_cluster_v4(par ? ax1 : ax0, __float_as_uint(wc.x),
                              __float_as_uint(wc.y), __float_as_uint(wc.z), 0u);
            }
        }
        cluster.sync();

        // per-warp resolve over the 8 CTA-winner slots
        ull a = 0;
        if (lane < CL) a = skey[par][lane];
        unsigned ch = (unsigned)(a >> 32);
        unsigned RH = __reduce_max_sync(0xffffffffu, ch);
        unsigned cl2 = (ch == RH) ? (unsigned)a : 0u;
        unsigned RL = __reduce_max_sync(0xffffffffu, cl2);
        ull W = ((ull)RH << 32) | RL;
        unsigned bal2 = __ballot_sync(0xffffffffu, (lane < CL) && (a == W));
        int slot = __ffs(bal2) - 1;
        float4 cc = sxyz[par][slot];       // LDS broadcast
        cx = cc.x; cy = cc.y; cz = cc.z;
        far = N - 1 - (int)RL;
    }
}

// ---------------------------------------------------------------------------
// 2) Fused ball query + grouping: one warp per center. Ball indices stay in
//    smem; the same warp then gathers and writes its 64 X0 columns.
// ---------------------------------------------------------------------------
__global__ void __launch_bounds__(256)
ballgroup_kernel(const float* __restrict__ xyz, const float* __restrict__ feat)
{
    __shared__ int sidx[8][NS];   // 8 warps per block

    int gw = (blockIdx.x * blockDim.x + threadIdx.x) >> 5;
    if (gw >= NG) return;
    int lane = threadIdx.x & 31;
    int w = (threadIdx.x >> 5) & 7;
    int b = gw >> 10;
    const float* __restrict__ p = xyz + (size_t)b * N * 3;
    float cx = g_newxyz[3 * gw], cy = g_newxyz[3 * gw + 1], cz = g_newxyz[3 * gw + 2];

    // --- ball: ordered first-NS collection via ballot ---
    int cnt = 0, first = 0;
    for (int base = 0; base < N; base += 32) {
        int j = base + lane;
        float dx = __fadd_rn(p[3 * j],     -cx);
        float dy = __fadd_rn(p[3 * j + 1], -cy);
        float dz = __fadd_rn(p[3 * j + 2], -cz);
        float d  = __fadd_rn(__fadd_rn(__fmul_rn(dx, dx), __fmul_rn(dy, dy)),
                             __fmul_rn(dz, dz));
        bool hit = d < 0.16f;
        unsigned mask = __ballot_sync(0xffffffffu, hit);
        if (mask) {
            if (cnt == 0) first = base + __ffs(mask) - 1;
            int pos = cnt + __popc(mask & ((1u << lane) - 1u));
            if (hit && pos < NS) sidx[w][pos] = j;
            cnt += __popc(mask);
            if (cnt >= NS) break;
        }
    }
    for (int q = cnt + lane; q < NS; q += 32) sidx[w][q] = first;
    __syncwarp();

    // --- group: each lane handles columns lane and lane+32 (coalesced) ---
    const float* fb = feat + (size_t)b * C * N;
#pragma unroll
    for (int h = 0; h < 2; h++) {
        int q = lane + h * 32;
        int j = sidx[w][q];
        int m = gw * NS + q;
        const float* pj = p + 3 * j;
        g_X0[(size_t)0 * M + m] = (pj[0] - cx) * 2.5f;
        g_X0[(size_t)1 * M + m] = (pj[1] - cy) * 2.5f;
        g_X0[(size_t)2 * M + m] = (pj[2] - cz) * 2.5f;
#pragma unroll
        for (int c = 0; c < C; c++)
            g_X0[(size_t)(3 + c) * M + m] = fb[(size_t)c * N + j];
    }
}

// ---------------------------------------------------------------------------
// 4a) Pass 1: BN1 partials from X0 (no Y1 materialization).
// ---------------------------------------------------------------------------
__global__ void __launch_bounds__(256)
gemm_p1(const float* __restrict__ Wg)
{
    __shared__ float Ws[CIN1 * 64];
    __shared__ float Xs[CIN1 * 128];

    const int tid = threadIdx.x;
    const int m0  = blockIdx.x * 128;
    const int tx  = tid & 15, ty = tid >> 4;

    for (int i = tid; i < CIN1 * 64; i += 256) {
        int c = i >> 6, o = i & 63;
        Ws[i] = Wg[o * CIN1 + c];
    }
    for (int i = tid; i < CIN1 * 32; i += 256) {
        int r = i >> 5, c4 = i & 31;
        *reinterpret_cast<float4*>(Xs + r * 128 + c4 * 4) =
            *reinterpret_cast<const float4*>(g_X0 + (size_t)r * M + m0 + c4 * 4);
    }
    __syncthreads();

    float acc[4][8];
#pragma unroll
    for (int i = 0; i < 4; i++)
#pragma unroll
        for (int jj = 0; jj < 8; jj++) acc[i][jj] = 0.f;

#pragma unroll 4
    for (int k = 0; k < CIN1; k++) {
        float4 w4 = *reinterpret_cast<const float4*>(Ws + k * 64 + ty * 4);
        float4 xa = *reinterpret_cast<const float4*>(Xs + k * 128 + tx * 8);
        float4 xb = *reinterpret_cast<const float4*>(Xs + k * 128 + tx * 8 + 4);
        float wr[4] = {w4.x, w4.y, w4.z, w4.w};
        float xr[8] = {xa.x, xa.y, xa.z, xa.w, xb.x, xb.y, xb.z, xb.w};
#pragma unroll
        for (int i = 0; i < 4; i++)
#pragma unroll
            for (int jj = 0; jj < 8; jj++)
                acc[i][jj] = fmaf(wr[i], xr[jj], acc[i][jj]);
    }

#pragma unroll
    for (int i = 0; i < 4; i++) {
        float sm = 0.f, sq = 0.f;
#pragma unroll
        for (int jj = 0; jj < 8; jj++) {
            sm += acc[i][jj];
            sq += acc[i][jj] * acc[i][jj];
        }
#pragma unroll
        for (int o = 8; o > 0; o >>= 1) {
            sm += __shfl_xor_sync(0xffffffffu, sm, o);
            sq += __shfl_xor_sync(0xffffffffu, sq, o);
        }
        if (tx == 0) {
            int o = ty * 4 + i;
            g_part[((size_t)o * GB + blockIdx.x) * 2]     = sm;
            g_part[((size_t)o * GB + blockIdx.x) * 2 + 1] = sq;
        }
    }
}

// ---------------------------------------------------------------------------
// 4b) Pass 2: recompute Y1 tile from X0 (bit-identical fmaf order), apply
//     BN1+ReLU in smem, then 64-out GEMM -> Y2 + BN2 partials.
// ---------------------------------------------------------------------------
constexpr int L2_SMEM = (CIN1 * 64 + 64 * 64 + CIN1 * 128 + 64 * 128) * 4;

__global__ void __launch_bounds__(256)
gemm_l2(const float* __restrict__ W1g, const float* __restrict__ W2g)
{
    extern __shared__ float sm_[];
    float* W1s = sm_;                          // [c][o] 19x64
    float* W2s = W1s + CIN1 * 64;              // [k][o] 64x64
    float* X0s = W2s + 64 * 64;                // [c][col] 19x128
    float* Y1s = X0s + CIN1 * 128;             // [k][col] 64x128

    const int tid = threadIdx.x;
    const int m0  = blockIdx.x * 128;
    const int tx  = tid & 15, ty = tid >> 4;

    for (int i = tid; i < CIN1 * 64; i += 256) {
        int c = i >> 6, o = i & 63;
        W1s[i] = W1g[o * CIN1 + c];
    }
    for (int i = tid; i < 64 * 64; i += 256) {
        int k = i >> 6, o = i & 63;
        W2s[i] = W2g[o * 64 + k];
    }
    for (int i = tid; i < CIN1 * 32; i += 256) {
        int r = i >> 5, c4 = i & 31;
        *reinterpret_cast<float4*>(X0s + r * 128 + c4 * 4) =
            *reinterpret_cast<const float4*>(g_X0 + (size_t)r * M + m0 + c4 * 4);
    }
    __syncthreads();

    // stage 1: Y1n = relu(bn1(W1 . X0)) — same acc order as pass 1
    {
        float a1[4][8];
#pragma unroll
        for (int i = 0; i < 4; i++)
#pragma unroll
            for (int jj = 0; jj < 8; jj++) a1[i][jj] = 0.f;
#pragma unroll 4
        for (int c = 0; c < CIN1; c++) {
            float4 w4 = *reinterpret_cast<const float4*>(W1s + c * 64 + ty * 4);
            float4 xa = *reinterpret_cast<const float4*>(X0s + c * 128 + tx * 8);
            float4 xb = *reinterpret_cast<const float4*>(X0s + c * 128 + tx * 8 + 4);
            float wr[4] = {w4.x, w4.y, w4.z, w4.w};
            float xr[8] = {xa.x, xa.y, xa.z, xa.w, xb.x, xb.y, xb.z, xb.w};
#pragma unroll
            for (int i = 0; i < 4; i++)
#pragma unroll
                for (int jj = 0; jj < 8; jj++)
                    a1[i][jj] = fmaf(wr[i], xr[jj], a1[i][jj]);
        }
#pragma unroll
        for (int i = 0; i < 4; i++) {
            int o = ty * 4 + i;
            float sc = g_scl1[o], sh = g_shf1[o];
            float4 va, vb;
            va.x = fmaxf(fmaf(a1[i][0], sc, sh), 0.f);
            va.y = fmaxf(fmaf(a1[i][1], sc, sh), 0.f);
            va.z = fmaxf(fmaf(a1[i][2], sc, sh), 0.f);
            va.w = fmaxf(fmaf(a1[i][3], sc, sh), 0.f);
            vb.x = fmaxf(fmaf(a1[i][4], sc, sh), 0.f);
            vb.y = fmaxf(fmaf(a1[i][5], sc, sh), 0.f);
            vb.z = fmaxf(fmaf(a1[i][6], sc, sh), 0.f);
            vb.w = fmaxf(fmaf(a1[i][7], sc, sh), 0.f);
            *reinterpret_cast<float4*>(Y1s + o * 128 + tx * 8)     = va;
            *reinterpret_cast<float4*>(Y1s + o * 128 + tx * 8 + 4) = vb;
        }
    }
    __syncthreads();

    // stage 2: Y2 = W2 . Y1n
    float acc[4][8];
#pragma unroll
    for (int i = 0; i < 4; i++)
#pragma unroll
        for (int jj = 0; jj < 8; jj++) acc[i][jj] = 0.f;

#pragma unroll 4
    for (int k = 0; k < 64; k++) {
        float4 w4 = *reinterpret_cast<const float4*>(W2s + k * 64 + ty * 4);
        float4 xa = *reinterpret_cast<const float4*>(Y1s + k * 128 + tx * 8);
        float4 xb = *reinterpret_cast<const float4*>(Y1s + k * 128 + tx * 8 + 4);
        float wr[4] = {w4.x, w4.y, w4.z, w4.w};
        float xr[8] = {xa.x, xa.y, xa.z, xa.w, xb.x, xb.y, xb.z, xb.w};
#pragma unroll
        for (int i = 0; i < 4; i++)
#pragma unroll
            for (int jj = 0; jj < 8; jj++)
                acc[i][jj] = fmaf(wr[i], xr[jj], acc[i][jj]);
    }

#pragma unroll
    for (int i = 0; i < 4; i++) {
        size_t off = (size_t)(ty * 4 + i) * M + m0 + tx * 8;
        *reinterpret_cast<float4*>(g_Y2 + off) =
            make_float4(acc[i][0], acc[i][1], acc[i][2], acc[i][3]);
        *reinterpret_cast<float4*>(g_Y2 + off + 4) =
            make_float4(acc[i][4], acc[i][5], acc[i][6], acc[i][7]);
    }

#pragma unroll
    for (int i = 0; i < 4; i++) {
        float sm = 0.f, sq = 0.f;
#pragma unroll
        for (int jj = 0; jj < 8; jj++) {
            sm += acc[i][jj];
            sq += acc[i][jj] * acc[i][jj];
        }
#pragma unroll
        for (int o = 8; o > 0; o >>= 1) {
            sm += __shfl_xor_sync(0xffffffffu, sm, o);
            sq += __shfl_xor_sync(0xffffffffu, sq, o);
        }
        if (tx == 0) {
            int o = ty * 4 + i;
            g_part[((size_t)o * GB + blockIdx.x) * 2]     = sm;
            g_part[((size_t)o * GB + blockIdx.x) * 2 + 1] = sq;
        }
    }
}

// ---------------------------------------------------------------------------
// 4c) Pass 3: merged 128-output GEMM, fused BN2+ReLU in, partials + group max
// ---------------------------------------------------------------------------
__global__ void __launch_bounds__(256)
gemm128_l3(const float* __restrict__ Wg)   // W3: (128,64) row-major
{
    __shared__ float Ws[64 * 128];   // 32 KB
    __shared__ float Xs[32 * 128];   // 16 KB

    const int tid = threadIdx.x;
    const int m0  = blockIdx.x * 128;
    const int tx  = tid & 15, ty = tid >> 4;

    for (int i = tid; i < 64 * 128; i += 256) {
        int k = i >> 7, o = i & 127;
        Ws[i] = Wg[o * 64 + k];
    }

    float acc[8][8];
#pragma unroll
    for (int i = 0; i < 8; i++)
#pragma unroll
        for (int jj = 0; jj < 8; jj++) acc[i][jj] = 0.f;

    for (int k0 = 0; k0 < 64; k0 += 32) {
        __syncthreads();
        for (int i = tid; i < 32 * 32; i += 256) {
            int r = i >> 5, c4 = i & 31;
            float4 v = *reinterpret_cast<const float4*>(
                g_Y2 + (size_t)(k0 + r) * M + m0 + c4 * 4);
            float sc = g_scl2[k0 + r], sh = g_shf2[k0 + r];
            v.x = fmaxf(fmaf(v.x, sc, sh), 0.f);
            v.y = fmaxf(fmaf(v.y, sc, sh), 0.f);
            v.z = fmaxf(fmaf(v.z, sc, sh), 0.f);
            v.w = fmaxf(fmaf(v.w, sc, sh), 0.f);
            *reinterpret_cast<float4*>(Xs + r * 128 + c4 * 4) = v;
        }
        __syncthreads();
#pragma unroll 4
        for (int k = 0; k < 32; k++) {
            float4 wa = *reinterpret_cast<const float4*>(Ws + (k0 + k) * 128 + ty * 8);
            float4 wb = *reinterpret_cast<const float4*>(Ws + (k0 + k) * 128 + ty * 8 + 4);
            float4 xa = *reinterpret_cast<const float4*>(Xs + k * 128 + tx * 8);
            float4 xb = *reinterpret_cast<const float4*>(Xs + k * 128 + tx * 8 + 4);
            float wr[8] = {wa.x, wa.y, wa.z, wa.w, wb.x, wb.y, wb.z, wb.w};
            float xr[8] = {xa.x, xa.y, xa.z, xa.w, xb.x, xb.y, xb.z, xb.w};
#pragma unroll
            for (int i = 0; i < 8; i++)
#pragma unroll
                for (int jj = 0; jj < 8; jj++)
                    acc[i][jj] = fmaf(wr[i], xr[jj], acc[i][jj]);
        }
    }

#pragma unroll
    for (int i = 0; i < 8; i++) {
        float sm = 0.f, sq = 0.f;
#pragma unroll
        for (int jj = 0; jj < 8; jj++) {
            sm += acc[i][jj];
            sq += acc[i][jj] * acc[i][jj];
        }
#pragma unroll
        for (int o = 8; o > 0; o >>= 1) {
            sm += __shfl_xor_sync(0xffffffffu, sm, o);
            sq += __shfl_xor_sync(0xffffffffu, sq, o);
        }
        if (tx == 0) {
            int o = ty * 8 + i;
            g_part[((size_t)o * GB + blockIdx.x) * 2]     = sm;
            g_part[((size_t)o * GB + blockIdx.x) * 2 + 1] = sq;
        }
    }

#pragma unroll
    for (int i = 0; i < 8; i++) {
        float mx = acc[i][0];
#pragma unroll
        for (int jj = 1; jj < 8; jj++) mx = fmaxf(mx, acc[i][jj]);
#pragma unroll
        for (int o = 4; o > 0; o >>= 1)
            mx = fmaxf(mx, __shfl_xor_sync(0xffffffffu, mx, o));
        if ((tx & 7) == 0) {
            int grp = (m0 >> 6) + (tx >> 3);
            g_max3[(size_t)(ty * 8 + i) * NG + grp] = mx;
        }
    }
}

// ---------------------------------------------------------------------------
// 5) BN stat finalize — parallel: one block per channel, fixed-order tree.
// ---------------------------------------------------------------------------
template<int LAYER>
__global__ void fin_par(const float* __restrict__ gam,
                        const float* __restrict__ bet)
{
    float* scl = (LAYER == 1) ? g_scl1 : (LAYER == 2) ? g_scl2 : g_scl3;
    float* shf = (LAYER == 1) ? g_shf1 : (LAYER == 2) ? g_shf2 : g_shf3;
    __shared__ float ssm[256], ssq[256];
    const int o = blockIdx.x;
    const int t = threadIdx.x;
    float sm = 0.f, sq = 0.f;
    const float* pp = g_part + (size_t)o * GB * 2;
    for (int i = t; i < GB; i += 256) {
        sm += pp[2 * i];
        sq += pp[2 * i + 1];
    }
    ssm[t] = sm; ssq[t] = sq;
    __syncthreads();
#pragma unroll
    for (int s2 = 128; s2 > 0; s2 >>= 1) {
        if (t < s2) { ssm[t] += ssm[t + s2]; ssq[t] += ssq[t + s2]; }
        __syncthreads();
    }
    if (t == 0) {
        float mean = ssm[0] * (1.0f / (float)M);
        float var  = ssq[0] * (1.0f / (float)M) - mean * mean;
        float sc = gam[o] * rsqrtf(var + 1e-5f);
        scl[o] = sc;
        shf[o] = fmaf(-mean, sc, bet[o]);
    }
}

// ---------------------------------------------------------------------------
// 6) Final: normalize+ReLU the group-max, write new_features
// ---------------------------------------------------------------------------
__global__ void out_feat_kernel(float* __restrict__ out)
{
    int idx = blockIdx.x * blockDim.x + threadIdx.x;
    if (idx >= 128 * NG) return;
    int o = idx >> 12;
    int g = idx & (NG - 1);
    int b = g >> 10, s = g & 1023;
    float v = fmaxf(fmaf(g_max3[idx], g_scl3[o], g_shf3[o]), 0.f);
    out[OUT_FEAT + ((size_t)(b * 128 + o)) * S + s] = v;
}

// ---------------------------------------------------------------------------
// Launch
// ---------------------------------------------------------------------------
extern "C" void kernel_launch(void* const* d_in, const int* in_sizes, int n_in,
                              void* d_out, int out_size)
{
    (void)in_sizes; (void)n_in; (void)out_size;
    const float* xyz  = (const float*)d_in[0];
    const float* feat = (const float*)d_in[1];
    const float* W1   = (const float*)d_in[2];
    const float* g1   = (const float*)d_in[3];
    const float* b1   = (const float*)d_in[4];
    const float* W2   = (const float*)d_in[5];
    const float* g2   = (const float*)d_in[6];
    const float* b2   = (const float*)d_in[7];
    const float* W3   = (const float*)d_in[8];
    const float* g3   = (const float*)d_in[9];
    const float* b3   = (const float*)d_in[10];
    float* out = (float*)d_out;

    cudaFuncSetAttribute(gemm_l2,
                         cudaFuncAttributeMaxDynamicSharedMemorySize, L2_SMEM);

    fps_kernel<<<B * CL, FPS_T>>>(xyz, out);
    ballgroup_kernel<<<(NG * 32) / 256, 256>>>(xyz, feat);

    gemm_p1<<<GB, 256>>>(W1);
    fin_par<1><<<64, 256>>>(g1, b1);

    gemm_l2<<<GB, 256, L2_SMEM>>>(W1, W2);
    fin_par<2><<<64, 256>>>(g2, b2);

    gemm128_l3<<<GB, 256>>>(W3);
    fin_par<3><<<128, 256>>>(g3, b3);

    out_feat_kernel<<<(128 * NG) / 256, 256>>>(out);
}

// round 16
// speedup vs baseline: 1.2562x; 1.0076x over previous
#include <cuda_runtime.h>
#include <cooperative_groups.h>
#include <cstdint>
#include <cstddef>

namespace cg = cooperative_groups;
typedef unsigned long long ull;

// ---------------------------------------------------------------------------
// Problem constants (fixed by setup_inputs)
// ---------------------------------------------------------------------------
constexpr int B  = 4;
constexpr int N  = 16384;
constexpr int C  = 16;
constexpr int S  = 1024;       // npoint
constexpr int NS = 64;         // NSAMPLE
constexpr int NG = B * S;                 // 4096 groups
constexpr int M  = NG * NS;               // 262144 columns
constexpr int CIN1 = 3 + C;               // 19
constexpr int GB = M / 128;               // 2048 gemm blocks

// FPS cluster decomposition (R9/R13 topology: 8 CTAs x 256 threads per batch)
constexpr int CL      = 8;
constexpr int FPS_T   = 256;
constexpr int PPT     = N / CL / FPS_T;   // 8 points per thread
constexpr int SLICE   = N / CL;           // 2048 points per CTA
constexpr int NW      = FPS_T / 32;       // 8 warps

// Output layout: new_xyz (B,S,3) | new_features (B,128,S) | inds (B,S), all f32
constexpr int OUT_FEAT = B * S * 3;              // 12288
constexpr int OUT_INDS = OUT_FEAT + B * 128 * S; // 536576

// ---------------------------------------------------------------------------
// Scratch (device globals; no runtime allocation allowed)
// ---------------------------------------------------------------------------
__device__ float g_newxyz[NG * 3];
__device__ float g_X0[(size_t)CIN1 * M];     // ~20 MB
__device__ float g_Y2[(size_t)64 * M];       // 67 MB
__device__ float g_max3[(size_t)128 * NG];   // 2 MB
__device__ float g_part[(size_t)128 * GB * 2];
__device__ float g_scl1[64],  g_shf1[64];
__device__ float g_scl2[64],  g_shf2[64];

// ---------------------------------------------------------------------------
// DSMEM primitives
// ---------------------------------------------------------------------------
__device__ __forceinline__ uint32_t mapa_sh(uint32_t local, uint32_t rank) {
    uint32_t r;
    asm("mapa.shared::cluster.u32 %0, %1, %2;" : "=r"(r) : "r"(local), "r"(rank));
    return r;
}
__device__ __forceinline__ void st_cluster_u64(uint32_t addr, ull v) {
    asm volatile("st.shared::cluster.u64 [%0], %1;" :: "r"(addr), "l"(v) : "memory");
}
__device__ __forceinline__ void st_cluster_v4(uint32_t addr, uint32_t a, uint32_t b2,
                                              uint32_t c2, uint32_t d2) {
    asm volatile("st.shared::cluster.v4.b32 [%0], {%1,%2,%3,%4};"
                 :: "r"(addr), "r"(a), "r"(b2), "r"(c2), "r"(d2) : "memory");
}

// ---------------------------------------------------------------------------
// 1) Furthest point sampling — R13 verbatim (hierarchical exchange +
//    cluster.sync, outputs on warp 1).
// ---------------------------------------------------------------------------
__global__ void __launch_bounds__(FPS_T, 1) __cluster_dims__(CL, 1, 1)
fps_kernel(const float* __restrict__ xyz, float* __restrict__ out)
{
    __shared__ ull    wkey[NW];
    __shared__ float4 wxyz[NW];
    __shared__ ull    skey[2][CL];
    __shared__ float4 sxyz[2][CL];

    cg::cluster_group cluster = cg::this_cluster();
    const unsigned rank = cluster.block_rank();
    const int b = blockIdx.x >> 3;
    const float* __restrict__ p = xyz + (size_t)b * N * 3;
    const int t = threadIdx.x;
    const int lane = t & 31, wid = t >> 5;
    const int jbase = rank * SLICE + t;

    float X[PPT], Y[PPT], Z[PPT], D[PPT];
#pragma unroll
    for (int k = 0; k < PPT; k++) {
        int j = jbase + k * FPS_T;
        X[k] = p[3 * j];
        Y[k] = p[3 * j + 1];
        Z[k] = p[3 * j + 2];
        D[k] = 1e10f;
    }

    uint32_t ak0 = 0, ak1 = 0, ax0 = 0, ax1 = 0;
    if (wid == 0) {
        uint32_t k0 = (uint32_t)__cvta_generic_to_shared(&skey[0][rank]);
        uint32_t k1 = (uint32_t)__cvta_generic_to_shared(&skey[1][rank]);
        uint32_t x0 = (uint32_t)__cvta_generic_to_shared(&sxyz[0][rank]);
        uint32_t x1 = (uint32_t)__cvta_generic_to_shared(&sxyz[1][rank]);
        uint32_t tr = (uint32_t)(lane & 7);
        ak0 = mapa_sh(k0, tr); ak1 = mapa_sh(k1, tr);
        ax0 = mapa_sh(x0, tr); ax1 = mapa_sh(x1, tr);
    }

    int far = 0;
    float cx = p[0], cy = p[1], cz = p[2];

    for (int i = 0; i < S; i++) {
        // outputs on warp 1 (all threads hold identical cx/cy/cz/far)
        if (rank == 0 && t == 32) {
            int gi = b * S + i;
            g_newxyz[3 * gi]     = cx;
            g_newxyz[3 * gi + 1] = cy;
            g_newxyz[3 * gi + 2] = cz;
            out[3 * gi]     = cx;
            out[3 * gi + 1] = cy;
            out[3 * gi + 2] = cz;
            out[OUT_INDS + gi] = (float)far;
        }

        // distance update + per-thread argmax with coordinate payload (exact)
        float best = -1.0f, bx = 0.f, by = 0.f, bz = 0.f;
        int bj = 0;
#pragma unroll
        for (int k = 0; k < PPT; k++) {
            float dx = __fadd_rn(X[k], -cx);
            float dy = __fadd_rn(Y[k], -cy);
            float dz = __fadd_rn(Z[k], -cz);
            float d  = __fadd_rn(__fadd_rn(__fmul_rn(dx, dx), __fmul_rn(dy, dy)),
                                 __fmul_rn(dz, dz));
            float nd = fminf(D[k], d);
            D[k] = nd;
            if (nd > best) {
                best = nd; bx = X[k]; by = Y[k]; bz = Z[k];
                bj = jbase + k * FPS_T;
            }
        }

        // warp argmax via two-stage REDUX; winner lane stores key+coords
        unsigned mb = __float_as_uint(best);                 // dist >= 0
        unsigned H  = __reduce_max_sync(0xffffffffu, mb);
        bool     el = (mb == H);
        unsigned lo = el ? (unsigned)(N - 1 - bj) : 0u;
        unsigned L  = __reduce_max_sync(0xffffffffu, lo);
        int wbj = N - 1 - (int)L;
        unsigned bal = __ballot_sync(0xffffffffu, el && (bj == wbj));
        int src = __ffs(bal) - 1;
        if (lane == src) {
            wkey[wid] = ((ull)H << 32) | L;
            wxyz[wid] = make_float4(bx, by, bz, 0.f);
        }
        __syncthreads();

        const int par = i & 1;
        if (wid == 0) {
            ull k2 = wkey[lane & 7];
            unsigned kh = (unsigned)(k2 >> 32);
            unsigned BH = __reduce_max_sync(0xffffffffu, kh);
            unsigned kl = (kh == BH) ? (unsigned)k2 : 0u;
            unsigned BL = __reduce_max_sync(0xffffffffu, kl);
            ull BW = ((ull)BH << 32) | BL;
            unsigned bw = __ballot_sync(0xffffffffu, (lane < 8) && (k2 == BW));
            int ws = __ffs(bw) - 1;
            float4 wc = wxyz[ws];          // LDS broadcast
            if (lane < CL) {
                st_cluster_u64(par ? ak1 : ak0, BW);
                st_cluster_v4(par ? ax1 : ax0, __float_as_uint(wc.x),
                              __float_as_uint(wc.y), __float_as_uint(wc.z), 0u);
            }
        }
        cluster.sync();

        // per-warp resolve over the 8 CTA-winner slots
        ull a = 0;
        if (lane < CL) a = skey[par][lane];
        unsigned ch = (unsigned)(a >> 32);
        unsigned RH = __reduce_max_sync(0xffffffffu, ch);
        unsigned cl2 = (ch == RH) ? (unsigned)a : 0u;
        unsigned RL = __reduce_max_sync(0xffffffffu, cl2);
        ull W = ((ull)RH << 32) | RL;
        unsigned bal2 = __ballot_sync(0xffffffffu, (lane < CL) && (a == W));
        int slot = __ffs(bal2) - 1;
        float4 cc = sxyz[par][slot];       // LDS broadcast
        cx = cc.x; cy = cc.y; cz = cc.z;
        far = N - 1 - (int)RL;
    }
}

// ---------------------------------------------------------------------------
// 2) Fused ball query + grouping (R13 verbatim): one warp per center.
// ---------------------------------------------------------------------------
__global__ void __launch_bounds__(256)
ballgroup_kernel(const float* __restrict__ xyz, const float* __restrict__ feat)
{
    __shared__ int sidx[8][NS];

    int gw = (blockIdx.x * blockDim.x + threadIdx.x) >> 5;
    if (gw >= NG) return;
    int lane = threadIdx.x & 31;
    int w = (threadIdx.x >> 5) & 7;
    int b = gw >> 10;
    const float* __restrict__ p = xyz + (size_t)b * N * 3;
    float cx = g_newxyz[3 * gw], cy = g_newxyz[3 * gw + 1], cz = g_newxyz[3 * gw + 2];

    int cnt = 0, first = 0;
    for (int base = 0; base < N; base += 32) {
        int j = base + lane;
        float dx = __fadd_rn(p[3 * j],     -cx);
        float dy = __fadd_rn(p[3 * j + 1], -cy);
        float dz = __fadd_rn(p[3 * j + 2], -cz);
        float d  = __fadd_rn(__fadd_rn(__fmul_rn(dx, dx), __fmul_rn(dy, dy)),
                             __fmul_rn(dz, dz));
        bool hit = d < 0.16f;
        unsigned mask = __ballot_sync(0xffffffffu, hit);
        if (mask) {
            if (cnt == 0) first = base + __ffs(mask) - 1;
            int pos = cnt + __popc(mask & ((1u << lane) - 1u));
            if (hit && pos < NS) sidx[w][pos] = j;
            cnt += __popc(mask);
            if (cnt >= NS) break;
        }
    }
    for (int q = cnt + lane; q < NS; q += 32) sidx[w][q] = first;
    __syncwarp();

    const float* fb = feat + (size_t)b * C * N;
#pragma unroll
    for (int h = 0; h < 2; h++) {
        int q = lane + h * 32;
        int j = sidx[w][q];
        int m = gw * NS + q;
        const float* pj = p + 3 * j;
        g_X0[(size_t)0 * M + m] = (pj[0] - cx) * 2.5f;
        g_X0[(size_t)1 * M + m] = (pj[1] - cy) * 2.5f;
        g_X0[(size_t)2 * M + m] = (pj[2] - cz) * 2.5f;
#pragma unroll
        for (int c = 0; c < C; c++)
            g_X0[(size_t)(3 + c) * M + m] = fb[(size_t)c * N + j];
    }
}

// ---------------------------------------------------------------------------
// 4a) Pass 1: BN1 partials from X0 (no Y1 materialization).
// ---------------------------------------------------------------------------
__global__ void __launch_bounds__(256)
gemm_p1(const float* __restrict__ Wg)
{
    __shared__ float Ws[CIN1 * 64];
    __shared__ float Xs[CIN1 * 128];

    const int tid = threadIdx.x;
    const int m0  = blockIdx.x * 128;
    const int tx  = tid & 15, ty = tid >> 4;

    for (int i = tid; i < CIN1 * 64; i += 256) {
        int c = i >> 6, o = i & 63;
        Ws[i] = Wg[o * CIN1 + c];
    }
    for (int i = tid; i < CIN1 * 32; i += 256) {
        int r = i >> 5, c4 = i & 31;
        *reinterpret_cast<float4*>(Xs + r * 128 + c4 * 4) =
            *reinterpret_cast<const float4*>(g_X0 + (size_t)r * M + m0 + c4 * 4);
    }
    __syncthreads();

    float acc[4][8];
#pragma unroll
    for (int i = 0; i < 4; i++)
#pragma unroll
        for (int jj = 0; jj < 8; jj++) acc[i][jj] = 0.f;

#pragma unroll 4
    for (int k = 0; k < CIN1; k++) {
        float4 w4 = *reinterpret_cast<const float4*>(Ws + k * 64 + ty * 4);
        float4 xa = *reinterpret_cast<const float4*>(Xs + k * 128 + tx * 8);
        float4 xb = *reinterpret_cast<const float4*>(Xs + k * 128 + tx * 8 + 4);
        float wr[4] = {w4.x, w4.y, w4.z, w4.w};
        float xr[8] = {xa.x, xa.y, xa.z, xa.w, xb.x, xb.y, xb.z, xb.w};
#pragma unroll
        for (int i = 0; i < 4; i++)
#pragma unroll
            for (int jj = 0; jj < 8; jj++)
                acc[i][jj] = fmaf(wr[i], xr[jj], acc[i][jj]);
    }

#pragma unroll
    for (int i = 0; i < 4; i++) {
        float sm = 0.f, sq = 0.f;
#pragma unroll
        for (int jj = 0; jj < 8; jj++) {
            sm += acc[i][jj];
            sq += acc[i][jj] * acc[i][jj];
        }
#pragma unroll
        for (int o = 8; o > 0; o >>= 1) {
            sm += __shfl_xor_sync(0xffffffffu, sm, o);
            sq += __shfl_xor_sync(0xffffffffu, sq, o);
        }
        if (tx == 0) {
            int o = ty * 4 + i;
            g_part[((size_t)o * GB + blockIdx.x) * 2]     = sm;
            g_part[((size_t)o * GB + blockIdx.x) * 2 + 1] = sq;
        }
    }
}

// ---------------------------------------------------------------------------
// 4b) Pass 2: recompute Y1 tile from X0, BN1+ReLU in smem, GEMM -> Y2 + partials
// ---------------------------------------------------------------------------
constexpr int L2_SMEM = (CIN1 * 64 + 64 * 64 + CIN1 * 128 + 64 * 128) * 4;

__global__ void __launch_bounds__(256)
gemm_l2(const float* __restrict__ W1g, const float* __restrict__ W2g)
{
    extern __shared__ float sm_[];
    float* W1s = sm_;
    float* W2s = W1s + CIN1 * 64;
    float* X0s = W2s + 64 * 64;
    float* Y1s = X0s + CIN1 * 128;

    const int tid = threadIdx.x;
    const int m0  = blockIdx.x * 128;
    const int tx  = tid & 15, ty = tid >> 4;

    for (int i = tid; i < CIN1 * 64; i += 256) {
        int c = i >> 6, o = i & 63;
        W1s[i] = W1g[o * CIN1 + c];
    }
    for (int i = tid; i < 64 * 64; i += 256) {
        int k = i >> 6, o = i & 63;
        W2s[i] = W2g[o * 64 + k];
    }
    for (int i = tid; i < CIN1 * 32; i += 256) {
        int r = i >> 5, c4 = i & 31;
        *reinterpret_cast<float4*>(X0s + r * 128 + c4 * 4) =
            *reinterpret_cast<const float4*>(g_X0 + (size_t)r * M + m0 + c4 * 4);
    }
    __syncthreads();

    {
        float a1[4][8];
#pragma unroll
        for (int i = 0; i < 4; i++)
#pragma unroll
            for (int jj = 0; jj < 8; jj++) a1[i][jj] = 0.f;
#pragma unroll 4
        for (int c = 0; c < CIN1; c++) {
            float4 w4 = *reinterpret_cast<const float4*>(W1s + c * 64 + ty * 4);
            float4 xa = *reinterpret_cast<const float4*>(X0s + c * 128 + tx * 8);
            float4 xb = *reinterpret_cast<const float4*>(X0s + c * 128 + tx * 8 + 4);
            float wr[4] = {w4.x, w4.y, w4.z, w4.w};
            float xr[8] = {xa.x, xa.y, xa.z, xa.w, xb.x, xb.y, xb.z, xb.w};
#pragma unroll
            for (int i = 0; i < 4; i++)
#pragma unroll
                for (int jj = 0; jj < 8; jj++)
                    a1[i][jj] = fmaf(wr[i], xr[jj], a1[i][jj]);
        }
#pragma unroll
        for (int i = 0; i < 4; i++) {
            int o = ty * 4 + i;
            float sc = g_scl1[o], sh = g_shf1[o];
            float4 va, vb;
            va.x = fmaxf(fmaf(a1[i][0], sc, sh), 0.f);
            va.y = fmaxf(fmaf(a1[i][1], sc, sh), 0.f);
            va.z = fmaxf(fmaf(a1[i][2], sc, sh), 0.f);
            va.w = fmaxf(fmaf(a1[i][3], sc, sh), 0.f);
            vb.x = fmaxf(fmaf(a1[i][4], sc, sh), 0.f);
            vb.y = fmaxf(fmaf(a1[i][5], sc, sh), 0.f);
            vb.z = fmaxf(fmaf(a1[i][6], sc, sh), 0.f);
            vb.w = fmaxf(fmaf(a1[i][7], sc, sh), 0.f);
            *reinterpret_cast<float4*>(Y1s + o * 128 + tx * 8)     = va;
            *reinterpret_cast<float4*>(Y1s + o * 128 + tx * 8 + 4) = vb;
        }
    }
    __syncthreads();

    float acc[4][8];
#pragma unroll
    for (int i = 0; i < 4; i++)
#pragma unroll
        for (int jj = 0; jj < 8; jj++) acc[i][jj] = 0.f;

#pragma unroll 4
    for (int k = 0; k < 64; k++) {
        float4 w4 = *reinterpret_cast<const float4*>(W2s + k * 64 + ty * 4);
        float4 xa = *reinterpret_cast<const float4*>(Y1s + k * 128 + tx * 8);
        float4 xb = *reinterpret_cast<const float4*>(Y1s + k * 128 + tx * 8 + 4);
        float wr[4] = {w4.x, w4.y, w4.z, w4.w};
        float xr[8] = {xa.x, xa.y, xa.z, xa.w, xb.x, xb.y, xb.z, xb.w};
#pragma unroll
        for (int i = 0; i < 4; i++)
#pragma unroll
            for (int jj = 0; jj < 8; jj++)
                acc[i][jj] = fmaf(wr[i], xr[jj], acc[i][jj]);
    }

#pragma unroll
    for (int i = 0; i < 4; i++) {
        size_t off = (size_t)(ty * 4 + i) * M + m0 + tx * 8;
        *reinterpret_cast<float4*>(g_Y2 + off) =
            make_float4(acc[i][0], acc[i][1], acc[i][2], acc[i][3]);
        *reinterpret_cast<float4*>(g_Y2 + off + 4) =
            make_float4(acc[i][4], acc[i][5], acc[i][6], acc[i][7]);
    }

#pragma unroll
    for (int i = 0; i < 4; i++) {
        float sm = 0.f, sq = 0.f;
#pragma unroll
        for (int jj = 0; jj < 8; jj++) {
            sm += acc[i][jj];
            sq += acc[i][jj] * acc[i][jj];
        }
#pragma unroll
        for (int o = 8; o > 0; o >>= 1) {
            sm += __shfl_xor_sync(0xffffffffu, sm, o);
            sq += __shfl_xor_sync(0xffffffffu, sq, o);
        }
        if (tx == 0) {
            int o = ty * 4 + i;
            g_part[((size_t)o * GB + blockIdx.x) * 2]     = sm;
            g_part[((size_t)o * GB + blockIdx.x) * 2 + 1] = sq;
        }
    }
}

// ---------------------------------------------------------------------------
// 4c) Pass 3: merged 128-output GEMM, fused BN2+ReLU in, partials + group max
// ---------------------------------------------------------------------------
__global__ void __launch_bounds__(256)
gemm128_l3(const float* __restrict__ Wg)
{
    __shared__ float Ws[64 * 128];
    __shared__ float Xs[32 * 128];

    const int tid = threadIdx.x;
    const int m0  = blockIdx.x * 128;
    const int tx  = tid & 15, ty = tid >> 4;

    for (int i = tid; i < 64 * 128; i += 256) {
        int k = i >> 7, o = i & 127;
        Ws[i] = Wg[o * 64 + k];
    }

    float acc[8][8];
#pragma unroll
    for (int i = 0; i < 8; i++)
#pragma unroll
        for (int jj = 0; jj < 8; jj++) acc[i][jj] = 0.f;

    for (int k0 = 0; k0 < 64; k0 += 32) {
        __syncthreads();
        for (int i = tid; i < 32 * 32; i += 256) {
            int r = i >> 5, c4 = i & 31;
            float4 v = *reinterpret_cast<const float4*>(
                g_Y2 + (size_t)(k0 + r) * M + m0 + c4 * 4);
            float sc = g_scl2[k0 + r], sh = g_shf2[k0 + r];
            v.x = fmaxf(fmaf(v.x, sc, sh), 0.f);
            v.y = fmaxf(fmaf(v.y, sc, sh), 0.f);
            v.z = fmaxf(fmaf(v.z, sc, sh), 0.f);
            v.w = fmaxf(fmaf(v.w, sc, sh), 0.f);
            *reinterpret_cast<float4*>(Xs + r * 128 + c4 * 4) = v;
        }
        __syncthreads();
#pragma unroll 4
        for (int k = 0; k < 32; k++) {
            float4 wa = *reinterpret_cast<const float4*>(Ws + (k0 + k) * 128 + ty * 8);
            float4 wb = *reinterpret_cast<const float4*>(Ws + (k0 + k) * 128 + ty * 8 + 4);
            float4 xa = *reinterpret_cast<const float4*>(Xs + k * 128 + tx * 8);
            float4 xb = *reinterpret_cast<const float4*>(Xs + k * 128 + tx * 8 + 4);
            float wr[8] = {wa.x, wa.y, wa.z, wa.w, wb.x, wb.y, wb.z, wb.w};
            float xr[8] = {xa.x, xa.y, xa.z, xa.w, xb.x, xb.y, xb.z, xb.w};
#pragma unroll
            for (int i = 0; i < 8; i++)
#pragma unroll
                for (int jj = 0; jj < 8; jj++)
                    acc[i][jj] = fmaf(wr[i], xr[jj], acc[i][jj]);
        }
    }

#pragma unroll
    for (int i = 0; i < 8; i++) {
        float sm = 0.f, sq = 0.f;
#pragma unroll
        for (int jj = 0; jj < 8; jj++) {
            sm += acc[i][jj];
            sq += acc[i][jj] * acc[i][jj];
        }
#pragma unroll
        for (int o = 8; o > 0; o >>= 1) {
            sm += __shfl_xor_sync(0xffffffffu, sm, o);
            sq += __shfl_xor_sync(0xffffffffu, sq, o);
        }
        if (tx == 0) {
            int o = ty * 8 + i;
            g_part[((size_t)o * GB + blockIdx.x) * 2]     = sm;
            g_part[((size_t)o * GB + blockIdx.x) * 2 + 1] = sq;
        }
    }

#pragma unroll
    for (int i = 0; i < 8; i++) {
        float mx = acc[i][0];
#pragma unroll
        for (int jj = 1; jj < 8; jj++) mx = fmaxf(mx, acc[i][jj]);
#pragma unroll
        for (int o = 4; o > 0; o >>= 1)
            mx = fmaxf(mx, __shfl_xor_sync(0xffffffffu, mx, o));
        if ((tx & 7) == 0) {
            int grp = (m0 >> 6) + (tx >> 3);
            g_max3[(size_t)(ty * 8 + i) * NG + grp] = mx;
        }
    }
}

// ---------------------------------------------------------------------------
// 5) BN stat finalize (layers 1-2) — one block per channel, fixed-order tree.
// ---------------------------------------------------------------------------
template<int LAYER>
__global__ void fin_par(const float* __restrict__ gam,
                        const float* __restrict__ bet)
{
    float* scl = (LAYER == 1) ? g_scl1 : g_scl2;
    float* shf = (LAYER == 1) ? g_shf1 : g_shf2;
    __shared__ float ssm[256], ssq[256];
    const int o = blockIdx.x;
    const int t = threadIdx.x;
    float sm = 0.f, sq = 0.f;
    const float* pp = g_part + (size_t)o * GB * 2;
    for (int i = t; i < GB; i += 256) {
        sm += pp[2 * i];
        sq += pp[2 * i + 1];
    }
    ssm[t] = sm; ssq[t] = sq;
    __syncthreads();
#pragma unroll
    for (int s2 = 128; s2 > 0; s2 >>= 1) {
        if (t < s2) { ssm[t] += ssm[t + s2]; ssq[t] += ssq[t + s2]; }
        __syncthreads();
    }
    if (t == 0) {
        float mean = ssm[0] * (1.0f / (float)M);
        float var  = ssq[0] * (1.0f / (float)M) - mean * mean;
        float sc = gam[o] * rsqrtf(var + 1e-5f);
        scl[o] = sc;
        shf[o] = fmaf(-mean, sc, bet[o]);
    }
}

// ---------------------------------------------------------------------------
// 6) Merged fin3 + output: one block per channel o — reduce BN3 partials,
//    then normalize+ReLU that channel's 4096 group-maxes and write out.
// ---------------------------------------------------------------------------
__global__ void __launch_bounds__(256)
fin3_out_kernel(const float* __restrict__ gam, const float* __restrict__ bet,
                float* __restrict__ out)
{
    __shared__ float ssm[256], ssq[256];
    __shared__ float s_sc, s_sh;
    const int o = blockIdx.x;
    const int t = threadIdx.x;
    float sm = 0.f, sq = 0.f;
    const float* pp = g_part + (size_t)o * GB * 2;
    for (int i = t; i < GB; i += 256) {
        sm += pp[2 * i];
        sq += pp[2 * i + 1];
    }
    ssm[t] = sm; ssq[t] = sq;
    __syncthreads();
#pragma unroll
    for (int s2 = 128; s2 > 0; s2 >>= 1) {
        if (t < s2) { ssm[t] += ssm[t + s2]; ssq[t] += ssq[t + s2]; }
        __syncthreads();
    }
    if (t == 0) {
        float mean = ssm[0] * (1.0f / (float)M);
        float var  = ssq[0] * (1.0f / (float)M) - mean * mean;
        float sc = gam[o] * rsqrtf(var + 1e-5f);
        s_sc = sc;
        s_sh = fmaf(-mean, sc, bet[o]);
    }
    __syncthreads();
    float sc = s_sc, sh = s_sh;
    for (int g = t; g < NG; g += 256) {
        int b = g >> 10, s = g & 1023;
        float v = fmaxf(fmaf(g_max3[(size_t)o * NG + g], sc, sh), 0.f);
        out[OUT_FEAT + ((size_t)(b * 128 + o)) * S + s] = v;
    }
}

// ---------------------------------------------------------------------------
// Launch
// ---------------------------------------------------------------------------
extern "C" void kernel_launch(void* const* d_in, const int* in_sizes, int n_in,
                              void* d_out, int out_size)
{
    (void)in_sizes; (void)n_in; (void)out_size;
    const float* xyz  = (const float*)d_in[0];
    const float* feat = (const float*)d_in[1];
    const float* W1   = (const float*)d_in[2];
    const float* g1   = (const float*)d_in[3];
    const float* b1   = (const float*)d_in[4];
    const float* W2   = (const float*)d_in[5];
    const float* g2   = (const float*)d_in[6];
    const float* b2   = (const float*)d_in[7];
    const float* W3   = (const float*)d_in[8];
    const float* g3   = (const float*)d_in[9];
    const float* b3   = (const float*)d_in[10];
    float* out = (float*)d_out;

    cudaFuncSetAttribute(gemm_l2,
                         cudaFuncAttributeMaxDynamicSharedMemorySize, L2_SMEM);

    fps_kernel<<<B * CL, FPS_T>>>(xyz, out);
    ballgroup_kernel<<<(NG * 32) / 256, 256>>>(xyz, feat);

    gemm_p1<<<GB, 256>>>(W1);
    fin_par<1><<<64, 256>>>(g1, b1);

    gemm_l2<<<GB, 256, L2_SMEM>>>(W1, W2);
    fin_par<2><<<64, 256>>>(g2, b2);

    gemm128_l3<<<GB, 256>>>(W3);
    fin3_out_kernel<<<128, 256>>>(g3, b3, out);
}